// round 12
// baseline (speedup 1.0000x reference)
#include <cuda_runtime.h>
#include <cuda_bf16.h>
#include <cstdint>

// B=16, TQ=TP=DQ=DP=1024
// out = softmax_over_Tp((p@W)@q^T) @ q, fp32 in/out.
// GEMM1/2: bf16 mma.sync 2-way split, 3 products (NN via ldmatrix.trans).
// GEMM3:   int8 mma.sync m16n8k32 with exact 16-bit fixed-point split (4 products,
//          warp-group product split), E scale 1/32512, q scale 8/32512.

static const long TT = 1048576L;

// ---------------- scratch ----------------
__device__ __nv_bfloat16 g_qThi[16777216], g_qTlo[16777216];
__device__ int8_t        g_qT8h[16777216], g_qT8l[16777216];
__device__ __nv_bfloat16 g_phi[16777216], g_plo[16777216];
__device__ __nv_bfloat16 g_Whi[1048576],  g_Wlo[1048576];
__device__ __nv_bfloat16 g_pWhi[16777216], g_pWlo[16777216];
__device__ int8_t        g_E8h[16777216],  g_E8l[16777216];
__device__ float g_S[16777216];

// ---------------- asm helpers ----------------
__device__ __forceinline__ uint32_t smem_u32(const void* p) {
    uint32_t a;
    asm("{ .reg .u64 t; cvta.to.shared.u64 t, %1; cvt.u32.u64 %0, t; }" : "=r"(a) : "l"(p));
    return a;
}
__device__ __forceinline__ void cp16(uint32_t s, const void* g) {
    asm volatile("cp.async.cg.shared.global [%0], [%1], 16;" :: "r"(s), "l"(g));
}
__device__ __forceinline__ void cp_commit() { asm volatile("cp.async.commit_group;"); }
template<int N>
__device__ __forceinline__ void cp_wait() { asm volatile("cp.async.wait_group %0;" :: "n"(N)); }

__device__ __forceinline__ void ldsm4(uint32_t (&r)[4], uint32_t a) {
    asm volatile("ldmatrix.sync.aligned.m8n8.x4.shared.b16 {%0,%1,%2,%3}, [%4];"
                 : "=r"(r[0]), "=r"(r[1]), "=r"(r[2]), "=r"(r[3]) : "r"(a));
}
__device__ __forceinline__ void ldsm4t(uint32_t (&r)[4], uint32_t a) {
    asm volatile("ldmatrix.sync.aligned.m8n8.x4.trans.shared.b16 {%0,%1,%2,%3}, [%4];"
                 : "=r"(r[0]), "=r"(r[1]), "=r"(r[2]), "=r"(r[3]) : "r"(a));
}
__device__ __forceinline__ void mma16816(float (&d)[4], const uint32_t (&a)[4],
                                         uint32_t b0, uint32_t b1) {
    asm volatile(
        "mma.sync.aligned.m16n8k16.row.col.f32.bf16.bf16.f32 "
        "{%0,%1,%2,%3}, {%4,%5,%6,%7}, {%8,%9}, {%0,%1,%2,%3};"
        : "+f"(d[0]), "+f"(d[1]), "+f"(d[2]), "+f"(d[3])
        : "r"(a[0]), "r"(a[1]), "r"(a[2]), "r"(a[3]), "r"(b0), "r"(b1));
}
__device__ __forceinline__ void imma16832(int (&d)[4], const uint32_t (&a)[4],
                                          uint32_t b0, uint32_t b1) {
    asm volatile(
        "mma.sync.aligned.m16n8k32.row.col.s32.s8.s8.s32 "
        "{%0,%1,%2,%3}, {%4,%5,%6,%7}, {%8,%9}, {%0,%1,%2,%3};"
        : "+r"(d[0]), "+r"(d[1]), "+r"(d[2]), "+r"(d[3])
        : "r"(a[0]), "r"(a[1]), "r"(a[2]), "r"(a[3]), "r"(b0), "r"(b1));
}

// ================= bf16 GEMM (NN): C[b][m][n] = sum_k A[b][m][k] * B[b][k][n] =================
static constexpr int MATB   = 128 * 128;
static constexpr int STAGEB = 4 * MATB;
static constexpr int SMEMSZ = 3 * STAGEB;  // 192KB

template<int STORE_SPLIT>
__global__ void __launch_bounds__(512, 1)
gemm_mma(const __nv_bfloat16* __restrict__ Ahi, const __nv_bfloat16* __restrict__ Alo, long sA,
         const __nv_bfloat16* __restrict__ Bhi, const __nv_bfloat16* __restrict__ Blo, long sB,
         float* __restrict__ Cf, __nv_bfloat16* __restrict__ Chi, __nv_bfloat16* __restrict__ Clo)
{
    extern __shared__ char smem[];
    const uint32_t sbase = smem_u32(smem);
    const int tid = threadIdx.x, lane = tid & 31, wid = tid >> 5;
    const int wm = wid >> 2, wn = wid & 3;
    const int b = blockIdx.z, m0 = blockIdx.y * 128, n0 = blockIdx.x * 128;

    const char* gA[2] = { (const char*)(Ahi + (size_t)b * sA + (size_t)m0 * 1024),
                          (const char*)(Alo + (size_t)b * sA + (size_t)m0 * 1024) };
    const char* gB[2] = { (const char*)(Bhi + (size_t)b * sB) + (size_t)n0 * 2,
                          (const char*)(Blo + (size_t)b * sB) + (size_t)n0 * 2 };

    const int crow[2] = { tid >> 3, (tid + 512) >> 3 };
    const int ccol = tid & 7;
    const int brow[2] = { tid >> 4, (tid + 512) >> 4 };
    const int bcol = tid & 15;

    auto issue_stage = [&](int buf, int kt) {
        const uint32_t sb = sbase + buf * STAGEB;
        const size_t kb = (size_t)kt * 128;
        #pragma unroll
        for (int m = 0; m < 2; m++) {
            const uint32_t mb = sb + m * MATB;
            #pragma unroll
            for (int t = 0; t < 2; t++) {
                const int r = crow[t];
                cp16(mb + r * 128 + ((ccol ^ (r & 7)) * 16),
                     gA[m] + (size_t)r * 2048 + kb + ccol * 16);
            }
        }
        #pragma unroll
        for (int m = 0; m < 2; m++) {
            const uint32_t mb = sb + (2 + m) * MATB;
            #pragma unroll
            for (int t = 0; t < 2; t++) {
                const int r = brow[t];
                cp16(mb + r * 256 + ((bcol ^ (r & 7)) * 16),
                     gB[m] + (size_t)(kt * 64 + r) * 2048 + bcol * 16);
            }
        }
        cp_commit();
    };

    float acc[2][4][4];
    #pragma unroll
    for (int i = 0; i < 2; i++)
        #pragma unroll
        for (int j = 0; j < 4; j++)
            #pragma unroll
            for (int t = 0; t < 4; t++) acc[i][j][t] = 0.f;

    issue_stage(0, 0);
    issue_stage(1, 1);

    const int lrow = lane & 15, lhi = lane >> 4;
    const int swz = lrow & 7;
    uint32_t koff[4];
    #pragma unroll
    for (int ks = 0; ks < 4; ks++) koff[ks] = (uint32_t)(((ks * 2 + lhi) ^ swz) * 16);

    const uint32_t arow_off = (uint32_t)(wm * 32 + lrow) * 128;

    uint32_t tb_base[2];
    #pragma unroll
    for (int nj = 0; nj < 2; nj++) {
        const int cn = wn * 4 + nj * 2 + lhi;
        tb_base[nj] = (uint32_t)(lrow * 256 + ((cn ^ swz) * 16));
    }

    #pragma unroll 1
    for (int i = 0; i < 16; i++) {
        if (i < 15) cp_wait<1>(); else cp_wait<0>();
        __syncthreads();
        if (i + 2 < 16) issue_stage((i + 2) % 3, i + 2);

        const uint32_t sb = sbase + (i % 3) * STAGEB;
        const uint32_t sAh = sb, sAl = sb + MATB, sBh = sb + 2 * MATB, sBl = sb + 3 * MATB;

        #pragma unroll
        for (int ks = 0; ks < 4; ks++) {
            const uint32_t kb = koff[ks];
            uint32_t ah[2][4], al[2][4];
            #pragma unroll
            for (int mi = 0; mi < 2; mi++) {
                const uint32_t ro = arow_off + (uint32_t)(mi * 16) * 128 + kb;
                ldsm4(ah[mi], sAh + ro);
                ldsm4(al[mi], sAl + ro);
            }
            uint32_t bh[4][2], bl[4][2];
            #pragma unroll
            for (int nj = 0; nj < 2; nj++) {
                const uint32_t ro = (uint32_t)(ks * 4096) + tb_base[nj];
                uint32_t r[4];
                ldsm4t(r, sBh + ro);
                bh[2*nj][0] = r[0]; bh[2*nj][1] = r[1];
                bh[2*nj+1][0] = r[2]; bh[2*nj+1][1] = r[3];
                ldsm4t(r, sBl + ro);
                bl[2*nj][0] = r[0]; bl[2*nj][1] = r[1];
                bl[2*nj+1][0] = r[2]; bl[2*nj+1][1] = r[3];
            }
            #pragma unroll
            for (int mi = 0; mi < 2; mi++)
                #pragma unroll
                for (int ni = 0; ni < 4; ni++) {
                    mma16816(acc[mi][ni], ah[mi], bh[ni][0], bh[ni][1]);
                    mma16816(acc[mi][ni], ah[mi], bl[ni][0], bl[ni][1]);
                    mma16816(acc[mi][ni], al[mi], bh[ni][0], bh[ni][1]);
                }
        }
    }

    const int er = m0 + wm * 32 + (lane >> 2);
    const int ec = n0 + wn * 32 + (lane & 3) * 2;
    #pragma unroll
    for (int mi = 0; mi < 2; mi++)
        #pragma unroll
        for (int ni = 0; ni < 4; ni++) {
            const int r0 = er + mi * 16, c = ec + ni * 8;
            const size_t o0 = (size_t)b * TT + (size_t)r0 * 1024 + c;
            const size_t o1 = o0 + 8 * 1024;
            if (STORE_SPLIT == 0) {
                *(float2*)(Cf + o0) = make_float2(acc[mi][ni][0], acc[mi][ni][1]);
                *(float2*)(Cf + o1) = make_float2(acc[mi][ni][2], acc[mi][ni][3]);
            } else {
                #pragma unroll
                for (int h = 0; h < 2; h++) {
                    const size_t o = h ? o1 : o0;
                    float x0 = acc[mi][ni][2*h], x1 = acc[mi][ni][2*h+1];
                    __nv_bfloat16 h0 = __float2bfloat16(x0);
                    __nv_bfloat16 h1 = __float2bfloat16(x1);
                    __nv_bfloat16 l0 = __float2bfloat16(x0 - __bfloat162float(h0));
                    __nv_bfloat16 l1 = __float2bfloat16(x1 - __bfloat162float(h1));
                    __nv_bfloat162 hp; hp.x = h0; hp.y = h1;
                    __nv_bfloat162 lp; lp.x = l0; lp.y = l1;
                    *(__nv_bfloat162*)(Chi + o) = hp;
                    *(__nv_bfloat162*)(Clo + o) = lp;
                }
            }
        }
}

// ================= int8 GEMM (NT): out[b][m][n] = sum_k E[b][m][k] * qT[b][n][k] =================
// 16-bit fixed point: X = hi*256 + lo (exact). Warp-group product split:
//   kg0 (A=hi plane): acc0 = hh, acc1 = hl ; kg1 (A=lo plane): acc0 = lh, acc1 = ll
// out = (hh*2^16 + (hl+lh)*2^8 + ll) * sE*sq,  sE = 1/32512, sq = 8/32512.
static constexpr int MAT_A8  = 128 * 128;               // 16KB A plane (128 rows x 128B)
static constexpr int MAT_B8  = 64 * 128;                 // 8KB  B plane (64 rows x 128B)
static constexpr int STAGE8  = 2 * MAT_A8 + 2 * MAT_B8;  // 48KB
static constexpr int SMEM8   = 3 * STAGE8;               // 144KB
static constexpr float SEQ   = 8.0f / (32512.0f * 32512.0f);

__global__ void __launch_bounds__(512, 1)
gemm_i8(const int8_t* __restrict__ Ahi, const int8_t* __restrict__ Alo,
        const int8_t* __restrict__ Bhi, const int8_t* __restrict__ Blo,
        float* __restrict__ Cf)
{
    extern __shared__ char smem[];
    const uint32_t sbase = smem_u32(smem);
    const int tid = threadIdx.x, lane = tid & 31, wid = tid >> 5;
    const int kg = wid >> 3, w8 = wid & 7;
    const int wm = w8 >> 1, wn = w8 & 1;      // 4m x 2n grid of 32x32 warp tiles
    const int b = blockIdx.z, m0 = blockIdx.y * 128, n0 = blockIdx.x * 64;

    const char* gA[2] = { (const char*)(Ahi + (size_t)b * TT + (size_t)m0 * 1024),
                          (const char*)(Alo + (size_t)b * TT + (size_t)m0 * 1024) };
    const char* gB[2] = { (const char*)(Bhi + (size_t)b * TT + (size_t)n0 * 1024),
                          (const char*)(Blo + (size_t)b * TT + (size_t)n0 * 1024) };

    // loaders: A plane 128 rows x 8 chunks (2 passes), B plane 64 rows x 8 chunks (1 pass)
    const int arw[2] = { tid >> 3, (tid + 512) >> 3 };
    const int acc8 = tid & 7;

    auto issue_stage = [&](int buf, int kt) {
        const uint32_t sb = sbase + buf * STAGE8;
        const size_t kb = (size_t)kt * 128;
        #pragma unroll
        for (int m = 0; m < 2; m++) {
            const uint32_t mb = sb + m * MAT_A8;
            #pragma unroll
            for (int t = 0; t < 2; t++) {
                const int r = arw[t];
                cp16(mb + r * 128 + ((acc8 ^ (r & 7)) * 16),
                     gA[m] + (size_t)r * 1024 + kb + acc8 * 16);
            }
        }
        #pragma unroll
        for (int m = 0; m < 2; m++) {
            const uint32_t mb = sb + 2 * MAT_A8 + m * MAT_B8;
            const int r = arw[0] & 63;          // tid>>3 in [0,64) for tid<512: take low 6 bits
            // only first 512 chunk-slots needed: 64 rows x 8 chunks = 512 == blockDim
            cp16(mb + r * 128 + ((acc8 ^ (r & 7)) * 16),
                 gB[m] + (size_t)r * 1024 + kb + acc8 * 16);
        }
        cp_commit();
    };

    int acc0[2][4][4], acc1[2][4][4];
    #pragma unroll
    for (int i = 0; i < 2; i++)
        #pragma unroll
        for (int j = 0; j < 4; j++)
            #pragma unroll
            for (int t = 0; t < 4; t++) { acc0[i][j][t] = 0; acc1[i][j][t] = 0; }

    issue_stage(0, 0);
    issue_stage(1, 1);

    const int lrow = lane & 15, lhi = lane >> 4;
    const int swz = lrow & 7;
    uint32_t koff[4];
    #pragma unroll
    for (int ks = 0; ks < 4; ks++) koff[ks] = (uint32_t)(((ks * 2 + lhi) ^ swz) * 16);

    const uint32_t arow_off = (uint32_t)(wm * 32 + lrow) * 128;
    const uint32_t brow_off = (uint32_t)(wn * 32 + lrow) * 128;
    const uint32_t sA_off = kg * MAT_A8;   // kg0 -> hi plane, kg1 -> lo plane

    #pragma unroll 1
    for (int i = 0; i < 8; i++) {
        if (i < 7) cp_wait<1>(); else cp_wait<0>();
        __syncthreads();
        if (i + 2 < 8) issue_stage((i + 2) % 3, i + 2);

        const uint32_t sb = sbase + (i % 3) * STAGE8;
        const uint32_t sA_ = sb + sA_off;
        const uint32_t sBh = sb + 2 * MAT_A8, sBl = sBh + MAT_B8;

        #pragma unroll
        for (int ks = 0; ks < 4; ks++) {
            const uint32_t kb = koff[ks];
            uint32_t av[2][4];
            #pragma unroll
            for (int mi = 0; mi < 2; mi++)
                ldsm4(av[mi], sA_ + arow_off + (uint32_t)(mi * 16) * 128 + kb);
            uint32_t bh[4][2], bl[4][2];
            #pragma unroll
            for (int nj = 0; nj < 2; nj++) {
                const uint32_t ro = brow_off + (uint32_t)(nj * 16) * 128 + kb;
                uint32_t r[4];
                ldsm4(r, sBh + ro);
                bh[2*nj][0] = r[0]; bh[2*nj+1][0] = r[1];
                bh[2*nj][1] = r[2]; bh[2*nj+1][1] = r[3];
                ldsm4(r, sBl + ro);
                bl[2*nj][0] = r[0]; bl[2*nj+1][0] = r[1];
                bl[2*nj][1] = r[2]; bl[2*nj+1][1] = r[3];
            }
            #pragma unroll
            for (int mi = 0; mi < 2; mi++)
                #pragma unroll
                for (int ni = 0; ni < 4; ni++) {
                    imma16832(acc0[mi][ni], av[mi], bh[ni][0], bh[ni][1]);  // myA * Bhi
                    imma16832(acc1[mi][ni], av[mi], bl[ni][0], bl[ni][1]);  // myA * Blo
                }
        }
    }

    // ---- combine kg partials through smem ----
    __syncthreads();
    int* red = (int*)smem;   // 8 warps x 2 accs x 1024 ints = 64KB
    const int* a0f = &acc0[0][0][0];
    const int* a1f = &acc1[0][0][0];
    if (kg == 1) {
        const int b0 = (w8 * 2 + 0) * 1024, b1 = (w8 * 2 + 1) * 1024;
        #pragma unroll
        for (int t = 0; t < 32; t++) {
            red[b0 + t * 32 + lane] = a0f[t];
            red[b1 + t * 32 + lane] = a1f[t];
        }
    }
    __syncthreads();
    if (kg == 0) {
        const int b0 = (w8 * 2 + 0) * 1024, b1 = (w8 * 2 + 1) * 1024;
        const int er = m0 + wm * 32 + (lane >> 2);
        const int ec = n0 + wn * 32 + (lane & 3) * 2;
        #pragma unroll
        for (int mi = 0; mi < 2; mi++)
            #pragma unroll
            for (int ni = 0; ni < 4; ni++) {
                float v[4];
                #pragma unroll
                for (int t = 0; t < 4; t++) {
                    const int fi = (mi * 4 + ni) * 4 + t;
                    const int hh = a0f[fi];
                    const int hl = a1f[fi];
                    const int lh = red[b0 + fi * 32 + lane];
                    const int ll = red[b1 + fi * 32 + lane];
                    v[t] = fmaf((float)hh, 65536.f,
                           fmaf((float)(hl + lh), 256.f, (float)ll)) * SEQ;
                }
                const int r0 = er + mi * 16, c = ec + ni * 8;
                const size_t o0 = (size_t)b * TT + (size_t)r0 * 1024 + c;
                *(float2*)(Cf + o0)            = make_float2(v[0], v[1]);
                *(float2*)(Cf + o0 + 8 * 1024) = make_float2(v[2], v[3]);
            }
    }
}

// ---------------- elementwise / transpose / softmax ----------------
struct alignas(8) bh4 { __nv_bfloat16 a, b, c, d; };

__device__ __forceinline__ void split1(float x, __nv_bfloat16& h, __nv_bfloat16& l) {
    h = __float2bfloat16(x);
    l = __float2bfloat16(x - __bfloat162float(h));
}
__device__ __forceinline__ void qsplit16(int v, int8_t& hi, int8_t& lo) {
    int l = (v << 24) >> 24;          // sign-extended low byte
    hi = (int8_t)((v - l) >> 8);
    lo = (int8_t)l;
}

__global__ void __launch_bounds__(256)
split2_kernel(const float* __restrict__ X, __nv_bfloat16* __restrict__ hi,
              __nv_bfloat16* __restrict__ lo)
{
    size_t i = (size_t)blockIdx.x * 256 + threadIdx.x;
    float4 v = ((const float4*)X)[i];
    bh4 h, l;
    split1(v.x, h.a, l.a); split1(v.y, h.b, l.b);
    split1(v.z, h.c, l.c); split1(v.w, h.d, l.d);
    ((bh4*)hi)[i] = h;
    ((bh4*)lo)[i] = l;
}

// transpose q -> qT: bf16 hi/lo (for GEMM2) + int8 hi/lo (for GEMM3)
__global__ void __launch_bounds__(256)
splitT_kernel(const float* __restrict__ in,
              __nv_bfloat16* __restrict__ thi, __nv_bfloat16* __restrict__ tlo,
              int8_t* __restrict__ t8h, int8_t* __restrict__ t8l)
{
    __shared__ float t[32][33];
    const int b = blockIdx.z;
    const float* I = in + (size_t)b * TT;
    const int x = blockIdx.x * 32 + threadIdx.x;
    const int y = blockIdx.y * 32 + threadIdx.y;
    #pragma unroll
    for (int j = 0; j < 32; j += 8)
        t[threadIdx.y + j][threadIdx.x] = I[(size_t)(y + j) * 1024 + x];
    __syncthreads();
    const int ox = blockIdx.y * 32 + threadIdx.x;
    const int oy = blockIdx.x * 32 + threadIdx.y;
    const size_t ob = (size_t)b * TT;
    #pragma unroll
    for (int j = 0; j < 32; j += 8) {
        float v = t[threadIdx.x][threadIdx.y + j];
        __nv_bfloat16 h, l; split1(v, h, l);
        const size_t o = ob + (size_t)(oy + j) * 1024 + ox;
        thi[o] = h;
        tlo[o] = l;
        int q16 = __float2int_rn(fminf(fmaxf(v * 4064.0f, -32512.f), 32512.f));
        int8_t qh, ql; qsplit16(q16, qh, ql);
        t8h[o] = qh;
        t8l[o] = ql;
    }
}

// Fused column softmax (over Tp = rows of S[b]) + exp + int8 16-bit quantization.
__global__ void __launch_bounds__(256)
softmax_exp_i8(const float* __restrict__ S,
               int8_t* __restrict__ E8h, int8_t* __restrict__ E8l)
{
    __shared__ float sm[8][32], sz[8][32];
    __shared__ float fm[32], fz[32];
    const int b = blockIdx.y;
    const int c = (threadIdx.x & 31);
    const int g = threadIdx.x >> 5;
    const int col = blockIdx.x * 32 + c;
    const float* Sb = S + (size_t)b * TT + col;

    float m = -1e30f, z = 0.f;
    #pragma unroll 4
    for (int r = g; r < 1024; r += 8) {
        float x = Sb[(size_t)r << 10];
        if (x > m) { z = z * __expf(m - x) + 1.f; m = x; }
        else       { z += __expf(x - m); }
    }
    sm[g][c] = m; sz[g][c] = z;
    __syncthreads();
    if (threadIdx.x < 32) {
        float M = sm[0][c];
        #pragma unroll
        for (int i = 1; i < 8; i++) M = fmaxf(M, sm[i][c]);
        float Z = 0.f;
        #pragma unroll
        for (int i = 0; i < 8; i++) Z += sz[i][c] * __expf(sm[i][c] - M);
        fm[c] = M; fz[c] = 1.0f / Z;
    }
    __syncthreads();
    const float Mf = fm[c], Rf = fz[c];
    int8_t* eh = E8h + (size_t)b * TT + col;
    int8_t* el = E8l + (size_t)b * TT + col;
    #pragma unroll 4
    for (int r = g; r < 1024; r += 8) {
        float x = Sb[(size_t)r << 10];
        float w = __expf(x - Mf) * Rf;          // in [0, 1]
        int v = __float2int_rn(w * 32512.0f);   // in [0, 32512]
        int8_t hh, ll; qsplit16(v, hh, ll);
        eh[(size_t)r << 10] = hh;
        el[(size_t)r << 10] = ll;
    }
}

// ---------------- launcher ----------------
extern "C" void kernel_launch(void* const* d_in, const int* in_sizes, int n_in,
                              void* d_out, int out_size)
{
    const float* q = (const float*)d_in[0];
    const float* p = (const float*)d_in[1];
    const float* W = (const float*)d_in[2];
    float* out = (float*)d_out;

    __nv_bfloat16 *qThi, *qTlo, *phi, *plo, *Whi, *Wlo, *pWhi, *pWlo;
    int8_t *qT8h, *qT8l, *E8h, *E8l;
    float *S;
    cudaGetSymbolAddress((void**)&qThi, g_qThi); cudaGetSymbolAddress((void**)&qTlo, g_qTlo);
    cudaGetSymbolAddress((void**)&qT8h, g_qT8h); cudaGetSymbolAddress((void**)&qT8l, g_qT8l);
    cudaGetSymbolAddress((void**)&phi, g_phi);   cudaGetSymbolAddress((void**)&plo, g_plo);
    cudaGetSymbolAddress((void**)&Whi, g_Whi);   cudaGetSymbolAddress((void**)&Wlo, g_Wlo);
    cudaGetSymbolAddress((void**)&pWhi, g_pWhi); cudaGetSymbolAddress((void**)&pWlo, g_pWlo);
    cudaGetSymbolAddress((void**)&E8h, g_E8h);   cudaGetSymbolAddress((void**)&E8l, g_E8l);
    cudaGetSymbolAddress((void**)&S, g_S);

    cudaFuncSetAttribute(gemm_mma<0>, cudaFuncAttributeMaxDynamicSharedMemorySize, SMEMSZ);
    cudaFuncSetAttribute(gemm_mma<1>, cudaFuncAttributeMaxDynamicSharedMemorySize, SMEMSZ);
    cudaFuncSetAttribute(gemm_i8,     cudaFuncAttributeMaxDynamicSharedMemorySize, SMEM8);

    const dim3 ggrid(8, 8, 16);

    split2_kernel<<<16384, 256>>>(p, phi, plo);
    splitT_kernel<<<dim3(32, 32, 16), dim3(32, 8)>>>(q, qThi, qTlo, qT8h, qT8l);
    split2_kernel<<<1024,  256>>>(W, Whi, Wlo);

    // GEMM1 (NN bf16): pW = p @ W, split-store
    gemm_mma<1><<<ggrid, 512, SMEMSZ>>>(phi, plo, TT, Whi, Wlo, 0L,
                                        nullptr, pWhi, pWlo);
    // GEMM2 (NN bf16): S = pW @ q^T (B = qT k-row-major) -> fp32
    gemm_mma<0><<<ggrid, 512, SMEMSZ>>>(pWhi, pWlo, TT, qThi, qTlo, TT,
                                        S, nullptr, nullptr);
    // softmax over Tp + exp + int16 fixed-point quantization
    softmax_exp_i8<<<dim3(32, 16), 256>>>(S, E8h, E8l);
    // GEMM3 (NT int8): out = E @ q  (A = E [Tp,Tq], B = qT [Dq,Tq] K-major)
    gemm_i8<<<dim3(16, 8, 16), 512, SMEM8>>>(E8h, E8l, qT8h, qT8l, out);
}

// round 13
// speedup vs baseline: 1.9691x; 1.9691x over previous
#include <cuda_runtime.h>
#include <cuda_bf16.h>
#include <cuda_fp16.h>
#include <cstdint>

// B=16, TQ=TP=DQ=DP=1024
// out = softmax_over_Tp((p@W)@q^T) @ q, fp32 in/out.
// GEMM1/2: bf16 mma.sync 2-way split, 3 products (NN via ldmatrix.trans).
// GEMM3:   fp16 mma.sync, 2 products: (Eh+El) @ qh  (E split exact to 2^-22,
//          q single fp16 plane; dropped E@(q-qh) term ~3e-4 rel).

static const long TT = 1048576L;

// ---------------- scratch ----------------
__device__ __nv_bfloat16 g_qThi[16777216], g_qTlo[16777216];
__device__ __half        g_qh16[16777216];
__device__ __nv_bfloat16 g_phi[16777216], g_plo[16777216];
__device__ __nv_bfloat16 g_Whi[1048576],  g_Wlo[1048576];
__device__ __nv_bfloat16 g_pWhi[16777216], g_pWlo[16777216];
__device__ __half        g_Eh[16777216],  g_El[16777216];
__device__ float g_S[16777216];

// ---------------- asm helpers ----------------
__device__ __forceinline__ uint32_t smem_u32(const void* p) {
    uint32_t a;
    asm("{ .reg .u64 t; cvta.to.shared.u64 t, %1; cvt.u32.u64 %0, t; }" : "=r"(a) : "l"(p));
    return a;
}
__device__ __forceinline__ void cp16(uint32_t s, const void* g) {
    asm volatile("cp.async.cg.shared.global [%0], [%1], 16;" :: "r"(s), "l"(g));
}
__device__ __forceinline__ void cp_commit() { asm volatile("cp.async.commit_group;"); }
template<int N>
__device__ __forceinline__ void cp_wait() { asm volatile("cp.async.wait_group %0;" :: "n"(N)); }

__device__ __forceinline__ void ldsm4(uint32_t (&r)[4], uint32_t a) {
    asm volatile("ldmatrix.sync.aligned.m8n8.x4.shared.b16 {%0,%1,%2,%3}, [%4];"
                 : "=r"(r[0]), "=r"(r[1]), "=r"(r[2]), "=r"(r[3]) : "r"(a));
}
__device__ __forceinline__ void ldsm4t(uint32_t (&r)[4], uint32_t a) {
    asm volatile("ldmatrix.sync.aligned.m8n8.x4.trans.shared.b16 {%0,%1,%2,%3}, [%4];"
                 : "=r"(r[0]), "=r"(r[1]), "=r"(r[2]), "=r"(r[3]) : "r"(a));
}
__device__ __forceinline__ void mma16816(float (&d)[4], const uint32_t (&a)[4],
                                         uint32_t b0, uint32_t b1) {
    asm volatile(
        "mma.sync.aligned.m16n8k16.row.col.f32.bf16.bf16.f32 "
        "{%0,%1,%2,%3}, {%4,%5,%6,%7}, {%8,%9}, {%0,%1,%2,%3};"
        : "+f"(d[0]), "+f"(d[1]), "+f"(d[2]), "+f"(d[3])
        : "r"(a[0]), "r"(a[1]), "r"(a[2]), "r"(a[3]), "r"(b0), "r"(b1));
}
__device__ __forceinline__ void mma16816h(float (&d)[4], const uint32_t (&a)[4],
                                          uint32_t b0, uint32_t b1) {
    asm volatile(
        "mma.sync.aligned.m16n8k16.row.col.f32.f16.f16.f32 "
        "{%0,%1,%2,%3}, {%4,%5,%6,%7}, {%8,%9}, {%0,%1,%2,%3};"
        : "+f"(d[0]), "+f"(d[1]), "+f"(d[2]), "+f"(d[3])
        : "r"(a[0]), "r"(a[1]), "r"(a[2]), "r"(a[3]), "r"(b0), "r"(b1));
}

// ================= bf16 GEMM (NN): C[b][m][n] = sum_k A[b][m][k] * B[b][k][n] =================
static constexpr int MATB   = 128 * 128;
static constexpr int STAGEB = 4 * MATB;
static constexpr int SMEMSZ = 3 * STAGEB;  // 192KB

template<int STORE_SPLIT>
__global__ void __launch_bounds__(512, 1)
gemm_mma(const __nv_bfloat16* __restrict__ Ahi, const __nv_bfloat16* __restrict__ Alo, long sA,
         const __nv_bfloat16* __restrict__ Bhi, const __nv_bfloat16* __restrict__ Blo, long sB,
         float* __restrict__ Cf, __nv_bfloat16* __restrict__ Chi, __nv_bfloat16* __restrict__ Clo)
{
    extern __shared__ char smem[];
    const uint32_t sbase = smem_u32(smem);
    const int tid = threadIdx.x, lane = tid & 31, wid = tid >> 5;
    const int wm = wid >> 2, wn = wid & 3;
    const int b = blockIdx.z, m0 = blockIdx.y * 128, n0 = blockIdx.x * 128;

    const char* gA[2] = { (const char*)(Ahi + (size_t)b * sA + (size_t)m0 * 1024),
                          (const char*)(Alo + (size_t)b * sA + (size_t)m0 * 1024) };
    const char* gB[2] = { (const char*)(Bhi + (size_t)b * sB) + (size_t)n0 * 2,
                          (const char*)(Blo + (size_t)b * sB) + (size_t)n0 * 2 };

    const int crow[2] = { tid >> 3, (tid + 512) >> 3 };
    const int ccol = tid & 7;
    const int brow[2] = { tid >> 4, (tid + 512) >> 4 };
    const int bcol = tid & 15;

    auto issue_stage = [&](int buf, int kt) {
        const uint32_t sb = sbase + buf * STAGEB;
        const size_t kb = (size_t)kt * 128;
        #pragma unroll
        for (int m = 0; m < 2; m++) {
            const uint32_t mb = sb + m * MATB;
            #pragma unroll
            for (int t = 0; t < 2; t++) {
                const int r = crow[t];
                cp16(mb + r * 128 + ((ccol ^ (r & 7)) * 16),
                     gA[m] + (size_t)r * 2048 + kb + ccol * 16);
            }
        }
        #pragma unroll
        for (int m = 0; m < 2; m++) {
            const uint32_t mb = sb + (2 + m) * MATB;
            #pragma unroll
            for (int t = 0; t < 2; t++) {
                const int r = brow[t];
                cp16(mb + r * 256 + ((bcol ^ (r & 7)) * 16),
                     gB[m] + (size_t)(kt * 64 + r) * 2048 + bcol * 16);
            }
        }
        cp_commit();
    };

    float acc[2][4][4];
    #pragma unroll
    for (int i = 0; i < 2; i++)
        #pragma unroll
        for (int j = 0; j < 4; j++)
            #pragma unroll
            for (int t = 0; t < 4; t++) acc[i][j][t] = 0.f;

    issue_stage(0, 0);
    issue_stage(1, 1);

    const int lrow = lane & 15, lhi = lane >> 4;
    const int swz = lrow & 7;
    uint32_t koff[4];
    #pragma unroll
    for (int ks = 0; ks < 4; ks++) koff[ks] = (uint32_t)(((ks * 2 + lhi) ^ swz) * 16);

    const uint32_t arow_off = (uint32_t)(wm * 32 + lrow) * 128;

    uint32_t tb_base[2];
    #pragma unroll
    for (int nj = 0; nj < 2; nj++) {
        const int cn = wn * 4 + nj * 2 + lhi;
        tb_base[nj] = (uint32_t)(lrow * 256 + ((cn ^ swz) * 16));
    }

    #pragma unroll 1
    for (int i = 0; i < 16; i++) {
        if (i < 15) cp_wait<1>(); else cp_wait<0>();
        __syncthreads();
        if (i + 2 < 16) issue_stage((i + 2) % 3, i + 2);

        const uint32_t sb = sbase + (i % 3) * STAGEB;
        const uint32_t sAh = sb, sAl = sb + MATB, sBh = sb + 2 * MATB, sBl = sb + 3 * MATB;

        #pragma unroll
        for (int ks = 0; ks < 4; ks++) {
            const uint32_t kb = koff[ks];
            uint32_t ah[2][4], al[2][4];
            #pragma unroll
            for (int mi = 0; mi < 2; mi++) {
                const uint32_t ro = arow_off + (uint32_t)(mi * 16) * 128 + kb;
                ldsm4(ah[mi], sAh + ro);
                ldsm4(al[mi], sAl + ro);
            }
            uint32_t bh[4][2], bl[4][2];
            #pragma unroll
            for (int nj = 0; nj < 2; nj++) {
                const uint32_t ro = (uint32_t)(ks * 4096) + tb_base[nj];
                uint32_t r[4];
                ldsm4t(r, sBh + ro);
                bh[2*nj][0] = r[0]; bh[2*nj][1] = r[1];
                bh[2*nj+1][0] = r[2]; bh[2*nj+1][1] = r[3];
                ldsm4t(r, sBl + ro);
                bl[2*nj][0] = r[0]; bl[2*nj][1] = r[1];
                bl[2*nj+1][0] = r[2]; bl[2*nj+1][1] = r[3];
            }
            #pragma unroll
            for (int mi = 0; mi < 2; mi++)
                #pragma unroll
                for (int ni = 0; ni < 4; ni++) {
                    mma16816(acc[mi][ni], ah[mi], bh[ni][0], bh[ni][1]);
                    mma16816(acc[mi][ni], ah[mi], bl[ni][0], bl[ni][1]);
                    mma16816(acc[mi][ni], al[mi], bh[ni][0], bh[ni][1]);
                }
        }
    }

    const int er = m0 + wm * 32 + (lane >> 2);
    const int ec = n0 + wn * 32 + (lane & 3) * 2;
    #pragma unroll
    for (int mi = 0; mi < 2; mi++)
        #pragma unroll
        for (int ni = 0; ni < 4; ni++) {
            const int r0 = er + mi * 16, c = ec + ni * 8;
            const size_t o0 = (size_t)b * TT + (size_t)r0 * 1024 + c;
            const size_t o1 = o0 + 8 * 1024;
            if (STORE_SPLIT == 0) {
                *(float2*)(Cf + o0) = make_float2(acc[mi][ni][0], acc[mi][ni][1]);
                *(float2*)(Cf + o1) = make_float2(acc[mi][ni][2], acc[mi][ni][3]);
            } else {
                #pragma unroll
                for (int h = 0; h < 2; h++) {
                    const size_t o = h ? o1 : o0;
                    float x0 = acc[mi][ni][2*h], x1 = acc[mi][ni][2*h+1];
                    __nv_bfloat16 h0 = __float2bfloat16(x0);
                    __nv_bfloat16 h1 = __float2bfloat16(x1);
                    __nv_bfloat16 l0 = __float2bfloat16(x0 - __bfloat162float(h0));
                    __nv_bfloat16 l1 = __float2bfloat16(x1 - __bfloat162float(h1));
                    __nv_bfloat162 hp; hp.x = h0; hp.y = h1;
                    __nv_bfloat162 lp; lp.x = l0; lp.y = l1;
                    *(__nv_bfloat162*)(Chi + o) = hp;
                    *(__nv_bfloat162*)(Clo + o) = lp;
                }
            }
        }
}

// ================= fp16 GEMM3 (NN, 2 products): out = (Eh+El) @ qh =================
// A = E [Tp, Tq] K-major rows, two fp16 planes. B = q [Tq, Dq] k-row-major, one fp16 plane.
static constexpr int STAGE3 = 3 * MATB;    // Eh 16KB + El 16KB + B 16KB = 48KB
static constexpr int SMEM3  = 3 * STAGE3;  // 144KB

__global__ void __launch_bounds__(512, 1)
gemm_f16(const __half* __restrict__ Ahi, const __half* __restrict__ Alo,
         const __half* __restrict__ Bq, float* __restrict__ Cf)
{
    extern __shared__ char smem[];
    const uint32_t sbase = smem_u32(smem);
    const int tid = threadIdx.x, lane = tid & 31, wid = tid >> 5;
    const int wm = wid >> 2, wn = wid & 3;
    const int b = blockIdx.z, m0 = blockIdx.y * 128, n0 = blockIdx.x * 128;

    const char* gA[2] = { (const char*)(Ahi + (size_t)b * TT + (size_t)m0 * 1024),
                          (const char*)(Alo + (size_t)b * TT + (size_t)m0 * 1024) };
    const char* gB = (const char*)(Bq + (size_t)b * TT) + (size_t)n0 * 2;

    const int crow[2] = { tid >> 3, (tid + 512) >> 3 };
    const int ccol = tid & 7;
    const int brow[2] = { tid >> 4, (tid + 512) >> 4 };
    const int bcol = tid & 15;

    auto issue_stage = [&](int buf, int kt) {
        const uint32_t sb = sbase + buf * STAGE3;
        const size_t kb = (size_t)kt * 128;
        #pragma unroll
        for (int m = 0; m < 2; m++) {
            const uint32_t mb = sb + m * MATB;
            #pragma unroll
            for (int t = 0; t < 2; t++) {
                const int r = crow[t];
                cp16(mb + r * 128 + ((ccol ^ (r & 7)) * 16),
                     gA[m] + (size_t)r * 2048 + kb + ccol * 16);
            }
        }
        {
            const uint32_t mb = sb + 2 * MATB;
            #pragma unroll
            for (int t = 0; t < 2; t++) {
                const int r = brow[t];
                cp16(mb + r * 256 + ((bcol ^ (r & 7)) * 16),
                     gB + (size_t)(kt * 64 + r) * 2048 + bcol * 16);
            }
        }
        cp_commit();
    };

    float acc[2][4][4];
    #pragma unroll
    for (int i = 0; i < 2; i++)
        #pragma unroll
        for (int j = 0; j < 4; j++)
            #pragma unroll
            for (int t = 0; t < 4; t++) acc[i][j][t] = 0.f;

    issue_stage(0, 0);
    issue_stage(1, 1);

    const int lrow = lane & 15, lhi = lane >> 4;
    const int swz = lrow & 7;
    uint32_t koff[4];
    #pragma unroll
    for (int ks = 0; ks < 4; ks++) koff[ks] = (uint32_t)(((ks * 2 + lhi) ^ swz) * 16);

    const uint32_t arow_off = (uint32_t)(wm * 32 + lrow) * 128;

    uint32_t tb_base[2];
    #pragma unroll
    for (int nj = 0; nj < 2; nj++) {
        const int cn = wn * 4 + nj * 2 + lhi;
        tb_base[nj] = (uint32_t)(lrow * 256 + ((cn ^ swz) * 16));
    }

    #pragma unroll 1
    for (int i = 0; i < 16; i++) {
        if (i < 15) cp_wait<1>(); else cp_wait<0>();
        __syncthreads();
        if (i + 2 < 16) issue_stage((i + 2) % 3, i + 2);

        const uint32_t sb = sbase + (i % 3) * STAGE3;
        const uint32_t sAh = sb, sAl = sb + MATB, sB_ = sb + 2 * MATB;

        #pragma unroll
        for (int ks = 0; ks < 4; ks++) {
            const uint32_t kb = koff[ks];
            uint32_t ah[2][4], al[2][4];
            #pragma unroll
            for (int mi = 0; mi < 2; mi++) {
                const uint32_t ro = arow_off + (uint32_t)(mi * 16) * 128 + kb;
                ldsm4(ah[mi], sAh + ro);
                ldsm4(al[mi], sAl + ro);
            }
            uint32_t bq[4][2];
            #pragma unroll
            for (int nj = 0; nj < 2; nj++) {
                const uint32_t ro = (uint32_t)(ks * 4096) + tb_base[nj];
                uint32_t r[4];
                ldsm4t(r, sB_ + ro);
                bq[2*nj][0] = r[0]; bq[2*nj][1] = r[1];
                bq[2*nj+1][0] = r[2]; bq[2*nj+1][1] = r[3];
            }
            #pragma unroll
            for (int mi = 0; mi < 2; mi++)
                #pragma unroll
                for (int ni = 0; ni < 4; ni++) {
                    mma16816h(acc[mi][ni], ah[mi], bq[ni][0], bq[ni][1]);  // Eh*q
                    mma16816h(acc[mi][ni], al[mi], bq[ni][0], bq[ni][1]);  // El*q
                }
        }
    }

    const int er = m0 + wm * 32 + (lane >> 2);
    const int ec = n0 + wn * 32 + (lane & 3) * 2;
    #pragma unroll
    for (int mi = 0; mi < 2; mi++)
        #pragma unroll
        for (int ni = 0; ni < 4; ni++) {
            const int r0 = er + mi * 16, c = ec + ni * 8;
            const size_t o0 = (size_t)b * TT + (size_t)r0 * 1024 + c;
            *(float2*)(Cf + o0)            = make_float2(acc[mi][ni][0], acc[mi][ni][1]);
            *(float2*)(Cf + o0 + 8 * 1024) = make_float2(acc[mi][ni][2], acc[mi][ni][3]);
        }
}

// ---------------- elementwise / transpose / softmax ----------------
struct alignas(8) bh4 { __nv_bfloat16 a, b, c, d; };

__device__ __forceinline__ void split1(float x, __nv_bfloat16& h, __nv_bfloat16& l) {
    h = __float2bfloat16(x);
    l = __float2bfloat16(x - __bfloat162float(h));
}

__global__ void __launch_bounds__(256)
split2_kernel(const float* __restrict__ X, __nv_bfloat16* __restrict__ hi,
              __nv_bfloat16* __restrict__ lo)
{
    size_t i = (size_t)blockIdx.x * 256 + threadIdx.x;
    float4 v = ((const float4*)X)[i];
    bh4 h, l;
    split1(v.x, h.a, l.a); split1(v.y, h.b, l.b);
    split1(v.z, h.c, l.c); split1(v.w, h.d, l.d);
    ((bh4*)hi)[i] = h;
    ((bh4*)lo)[i] = l;
}

// q prep: straight fp16 plane (GEMM3 B) + transposed bf16 hi/lo (GEMM2 B)
__global__ void __launch_bounds__(256)
splitT_kernel(const float* __restrict__ in, __half* __restrict__ oh16,
              __nv_bfloat16* __restrict__ thi, __nv_bfloat16* __restrict__ tlo)
{
    __shared__ float t[32][33];
    const int b = blockIdx.z;
    const float* I = in + (size_t)b * TT;
    const int x = blockIdx.x * 32 + threadIdx.x;
    const int y = blockIdx.y * 32 + threadIdx.y;
    const size_t ob = (size_t)b * TT;
    #pragma unroll
    for (int j = 0; j < 32; j += 8) {
        float v = I[(size_t)(y + j) * 1024 + x];
        t[threadIdx.y + j][threadIdx.x] = v;
        oh16[ob + (size_t)(y + j) * 1024 + x] = __float2half(v);
    }
    __syncthreads();
    const int ox = blockIdx.y * 32 + threadIdx.x;
    const int oy = blockIdx.x * 32 + threadIdx.y;
    #pragma unroll
    for (int j = 0; j < 32; j += 8) {
        float v = t[threadIdx.x][threadIdx.y + j];
        __nv_bfloat16 h, l; split1(v, h, l);
        thi[ob + (size_t)(oy + j) * 1024 + ox] = h;
        tlo[ob + (size_t)(oy + j) * 1024 + ox] = l;
    }
}

// Fused column softmax (over Tp = rows of S[b]) + exp + fp16 split of weights.
__global__ void __launch_bounds__(256)
softmax_exp_f16(const float* __restrict__ S,
                __half* __restrict__ Eh, __half* __restrict__ El)
{
    __shared__ float sm[8][32], sz[8][32];
    __shared__ float fm[32], fz[32];
    const int b = blockIdx.y;
    const int c = (threadIdx.x & 31);
    const int g = threadIdx.x >> 5;
    const int col = blockIdx.x * 32 + c;
    const float* Sb = S + (size_t)b * TT + col;

    float m = -1e30f, z = 0.f;
    #pragma unroll 4
    for (int r = g; r < 1024; r += 8) {
        float x = Sb[(size_t)r << 10];
        if (x > m) { z = z * __expf(m - x) + 1.f; m = x; }
        else       { z += __expf(x - m); }
    }
    sm[g][c] = m; sz[g][c] = z;
    __syncthreads();
    if (threadIdx.x < 32) {
        float M = sm[0][c];
        #pragma unroll
        for (int i = 1; i < 8; i++) M = fmaxf(M, sm[i][c]);
        float Z = 0.f;
        #pragma unroll
        for (int i = 0; i < 8; i++) Z += sz[i][c] * __expf(sm[i][c] - M);
        fm[c] = M; fz[c] = 1.0f / Z;
    }
    __syncthreads();
    const float Mf = fm[c], Rf = fz[c];
    __half* eh = Eh + (size_t)b * TT + col;
    __half* el = El + (size_t)b * TT + col;
    #pragma unroll 4
    for (int r = g; r < 1024; r += 8) {
        float x = Sb[(size_t)r << 10];
        float w = __expf(x - Mf) * Rf;
        __half h = __float2half(w);
        __half l = __float2half(w - __half2float(h));
        eh[(size_t)r << 10] = h;
        el[(size_t)r << 10] = l;
    }
}

// ---------------- launcher ----------------
extern "C" void kernel_launch(void* const* d_in, const int* in_sizes, int n_in,
                              void* d_out, int out_size)
{
    const float* q = (const float*)d_in[0];
    const float* p = (const float*)d_in[1];
    const float* W = (const float*)d_in[2];
    float* out = (float*)d_out;

    __nv_bfloat16 *qThi, *qTlo, *phi, *plo, *Whi, *Wlo, *pWhi, *pWlo;
    __half *qh16, *Eh, *El;
    float *S;
    cudaGetSymbolAddress((void**)&qThi, g_qThi); cudaGetSymbolAddress((void**)&qTlo, g_qTlo);
    cudaGetSymbolAddress((void**)&qh16, g_qh16);
    cudaGetSymbolAddress((void**)&phi, g_phi);   cudaGetSymbolAddress((void**)&plo, g_plo);
    cudaGetSymbolAddress((void**)&Whi, g_Whi);   cudaGetSymbolAddress((void**)&Wlo, g_Wlo);
    cudaGetSymbolAddress((void**)&pWhi, g_pWhi); cudaGetSymbolAddress((void**)&pWlo, g_pWlo);
    cudaGetSymbolAddress((void**)&Eh, g_Eh);     cudaGetSymbolAddress((void**)&El, g_El);
    cudaGetSymbolAddress((void**)&S, g_S);

    cudaFuncSetAttribute(gemm_mma<0>, cudaFuncAttributeMaxDynamicSharedMemorySize, SMEMSZ);
    cudaFuncSetAttribute(gemm_mma<1>, cudaFuncAttributeMaxDynamicSharedMemorySize, SMEMSZ);
    cudaFuncSetAttribute(gemm_f16,    cudaFuncAttributeMaxDynamicSharedMemorySize, SMEM3);

    const dim3 ggrid(8, 8, 16);

    split2_kernel<<<16384, 256>>>(p, phi, plo);
    splitT_kernel<<<dim3(32, 32, 16), dim3(32, 8)>>>(q, qh16, qThi, qTlo);
    split2_kernel<<<1024,  256>>>(W, Whi, Wlo);

    // GEMM1 (NN bf16): pW = p @ W, split-store
    gemm_mma<1><<<ggrid, 512, SMEMSZ>>>(phi, plo, TT, Whi, Wlo, 0L,
                                        nullptr, pWhi, pWlo);
    // GEMM2 (NN bf16): S = pW @ q^T (B = qT k-row-major) -> fp32
    gemm_mma<0><<<ggrid, 512, SMEMSZ>>>(pWhi, pWlo, TT, qThi, qTlo, TT,
                                        S, nullptr, nullptr);
    // softmax over Tp + exp + fp16 split of weights
    softmax_exp_f16<<<dim3(32, 16), 256>>>(S, Eh, El);
    // GEMM3 (NN fp16, 2 products): out = (Eh+El) @ qh
    gemm_f16<<<ggrid, 512, SMEM3>>>(Eh, El, qh16, out);
}

// round 14
// speedup vs baseline: 2.1716x; 1.1029x over previous
#include <cuda_runtime.h>
#include <cuda_bf16.h>
#include <cuda_fp16.h>
#include <cstdint>

// B=16, TQ=TP=DQ=DP=1024
// out = softmax_over_Tp((p@W)@q^T) @ q, fp32 in/out.
// GEMM1/2: bf16 mma.sync 2-way split, 3 products (NN via ldmatrix.trans).
// GEMM3:   fp16 mma.sync, SINGLE product: Eh @ qh (err ~2.4e-4 rel, combined ~3.2e-4).

static const long TT = 1048576L;

// ---------------- scratch ----------------
__device__ __nv_bfloat16 g_qThi[16777216], g_qTlo[16777216];
__device__ __half        g_qh16[16777216];
__device__ __nv_bfloat16 g_phi[16777216], g_plo[16777216];
__device__ __nv_bfloat16 g_Whi[1048576],  g_Wlo[1048576];
__device__ __nv_bfloat16 g_pWhi[16777216], g_pWlo[16777216];
__device__ __half        g_Eh[16777216];
__device__ float g_S[16777216];

// ---------------- asm helpers ----------------
__device__ __forceinline__ uint32_t smem_u32(const void* p) {
    uint32_t a;
    asm("{ .reg .u64 t; cvta.to.shared.u64 t, %1; cvt.u32.u64 %0, t; }" : "=r"(a) : "l"(p));
    return a;
}
__device__ __forceinline__ void cp16(uint32_t s, const void* g) {
    asm volatile("cp.async.cg.shared.global [%0], [%1], 16;" :: "r"(s), "l"(g));
}
__device__ __forceinline__ void cp_commit() { asm volatile("cp.async.commit_group;"); }
template<int N>
__device__ __forceinline__ void cp_wait() { asm volatile("cp.async.wait_group %0;" :: "n"(N)); }

__device__ __forceinline__ void ldsm4(uint32_t (&r)[4], uint32_t a) {
    asm volatile("ldmatrix.sync.aligned.m8n8.x4.shared.b16 {%0,%1,%2,%3}, [%4];"
                 : "=r"(r[0]), "=r"(r[1]), "=r"(r[2]), "=r"(r[3]) : "r"(a));
}
__device__ __forceinline__ void ldsm4t(uint32_t (&r)[4], uint32_t a) {
    asm volatile("ldmatrix.sync.aligned.m8n8.x4.trans.shared.b16 {%0,%1,%2,%3}, [%4];"
                 : "=r"(r[0]), "=r"(r[1]), "=r"(r[2]), "=r"(r[3]) : "r"(a));
}
__device__ __forceinline__ void mma16816(float (&d)[4], const uint32_t (&a)[4],
                                         uint32_t b0, uint32_t b1) {
    asm volatile(
        "mma.sync.aligned.m16n8k16.row.col.f32.bf16.bf16.f32 "
        "{%0,%1,%2,%3}, {%4,%5,%6,%7}, {%8,%9}, {%0,%1,%2,%3};"
        : "+f"(d[0]), "+f"(d[1]), "+f"(d[2]), "+f"(d[3])
        : "r"(a[0]), "r"(a[1]), "r"(a[2]), "r"(a[3]), "r"(b0), "r"(b1));
}
__device__ __forceinline__ void mma16816h(float (&d)[4], const uint32_t (&a)[4],
                                          uint32_t b0, uint32_t b1) {
    asm volatile(
        "mma.sync.aligned.m16n8k16.row.col.f32.f16.f16.f32 "
        "{%0,%1,%2,%3}, {%4,%5,%6,%7}, {%8,%9}, {%0,%1,%2,%3};"
        : "+f"(d[0]), "+f"(d[1]), "+f"(d[2]), "+f"(d[3])
        : "r"(a[0]), "r"(a[1]), "r"(a[2]), "r"(a[3]), "r"(b0), "r"(b1));
}

// ================= bf16 GEMM (NN): C[b][m][n] = sum_k A[b][m][k] * B[b][k][n] =================
static constexpr int MATB   = 128 * 128;
static constexpr int STAGEB = 4 * MATB;
static constexpr int SMEMSZ = 3 * STAGEB;  // 192KB

template<int STORE_SPLIT>
__global__ void __launch_bounds__(512, 1)
gemm_mma(const __nv_bfloat16* __restrict__ Ahi, const __nv_bfloat16* __restrict__ Alo, long sA,
         const __nv_bfloat16* __restrict__ Bhi, const __nv_bfloat16* __restrict__ Blo, long sB,
         float* __restrict__ Cf, __nv_bfloat16* __restrict__ Chi, __nv_bfloat16* __restrict__ Clo)
{
    extern __shared__ char smem[];
    const uint32_t sbase = smem_u32(smem);
    const int tid = threadIdx.x, lane = tid & 31, wid = tid >> 5;
    const int wm = wid >> 2, wn = wid & 3;
    const int b = blockIdx.z, m0 = blockIdx.y * 128, n0 = blockIdx.x * 128;

    const char* gA[2] = { (const char*)(Ahi + (size_t)b * sA + (size_t)m0 * 1024),
                          (const char*)(Alo + (size_t)b * sA + (size_t)m0 * 1024) };
    const char* gB[2] = { (const char*)(Bhi + (size_t)b * sB) + (size_t)n0 * 2,
                          (const char*)(Blo + (size_t)b * sB) + (size_t)n0 * 2 };

    const int crow[2] = { tid >> 3, (tid + 512) >> 3 };
    const int ccol = tid & 7;
    const int brow[2] = { tid >> 4, (tid + 512) >> 4 };
    const int bcol = tid & 15;

    auto issue_stage = [&](int buf, int kt) {
        const uint32_t sb = sbase + buf * STAGEB;
        const size_t kb = (size_t)kt * 128;
        #pragma unroll
        for (int m = 0; m < 2; m++) {
            const uint32_t mb = sb + m * MATB;
            #pragma unroll
            for (int t = 0; t < 2; t++) {
                const int r = crow[t];
                cp16(mb + r * 128 + ((ccol ^ (r & 7)) * 16),
                     gA[m] + (size_t)r * 2048 + kb + ccol * 16);
            }
        }
        #pragma unroll
        for (int m = 0; m < 2; m++) {
            const uint32_t mb = sb + (2 + m) * MATB;
            #pragma unroll
            for (int t = 0; t < 2; t++) {
                const int r = brow[t];
                cp16(mb + r * 256 + ((bcol ^ (r & 7)) * 16),
                     gB[m] + (size_t)(kt * 64 + r) * 2048 + bcol * 16);
            }
        }
        cp_commit();
    };

    float acc[2][4][4];
    #pragma unroll
    for (int i = 0; i < 2; i++)
        #pragma unroll
        for (int j = 0; j < 4; j++)
            #pragma unroll
            for (int t = 0; t < 4; t++) acc[i][j][t] = 0.f;

    issue_stage(0, 0);
    issue_stage(1, 1);

    const int lrow = lane & 15, lhi = lane >> 4;
    const int swz = lrow & 7;
    uint32_t koff[4];
    #pragma unroll
    for (int ks = 0; ks < 4; ks++) koff[ks] = (uint32_t)(((ks * 2 + lhi) ^ swz) * 16);

    const uint32_t arow_off = (uint32_t)(wm * 32 + lrow) * 128;

    uint32_t tb_base[2];
    #pragma unroll
    for (int nj = 0; nj < 2; nj++) {
        const int cn = wn * 4 + nj * 2 + lhi;
        tb_base[nj] = (uint32_t)(lrow * 256 + ((cn ^ swz) * 16));
    }

    #pragma unroll 1
    for (int i = 0; i < 16; i++) {
        if (i < 15) cp_wait<1>(); else cp_wait<0>();
        __syncthreads();
        if (i + 2 < 16) issue_stage((i + 2) % 3, i + 2);

        const uint32_t sb = sbase + (i % 3) * STAGEB;
        const uint32_t sAh = sb, sAl = sb + MATB, sBh = sb + 2 * MATB, sBl = sb + 3 * MATB;

        #pragma unroll
        for (int ks = 0; ks < 4; ks++) {
            const uint32_t kb = koff[ks];
            uint32_t ah[2][4], al[2][4];
            #pragma unroll
            for (int mi = 0; mi < 2; mi++) {
                const uint32_t ro = arow_off + (uint32_t)(mi * 16) * 128 + kb;
                ldsm4(ah[mi], sAh + ro);
                ldsm4(al[mi], sAl + ro);
            }
            uint32_t bh[4][2], bl[4][2];
            #pragma unroll
            for (int nj = 0; nj < 2; nj++) {
                const uint32_t ro = (uint32_t)(ks * 4096) + tb_base[nj];
                uint32_t r[4];
                ldsm4t(r, sBh + ro);
                bh[2*nj][0] = r[0]; bh[2*nj][1] = r[1];
                bh[2*nj+1][0] = r[2]; bh[2*nj+1][1] = r[3];
                ldsm4t(r, sBl + ro);
                bl[2*nj][0] = r[0]; bl[2*nj][1] = r[1];
                bl[2*nj+1][0] = r[2]; bl[2*nj+1][1] = r[3];
            }
            #pragma unroll
            for (int mi = 0; mi < 2; mi++)
                #pragma unroll
                for (int ni = 0; ni < 4; ni++) {
                    mma16816(acc[mi][ni], ah[mi], bh[ni][0], bh[ni][1]);
                    mma16816(acc[mi][ni], ah[mi], bl[ni][0], bl[ni][1]);
                    mma16816(acc[mi][ni], al[mi], bh[ni][0], bh[ni][1]);
                }
        }
    }

    const int er = m0 + wm * 32 + (lane >> 2);
    const int ec = n0 + wn * 32 + (lane & 3) * 2;
    #pragma unroll
    for (int mi = 0; mi < 2; mi++)
        #pragma unroll
        for (int ni = 0; ni < 4; ni++) {
            const int r0 = er + mi * 16, c = ec + ni * 8;
            const size_t o0 = (size_t)b * TT + (size_t)r0 * 1024 + c;
            const size_t o1 = o0 + 8 * 1024;
            if (STORE_SPLIT == 0) {
                *(float2*)(Cf + o0) = make_float2(acc[mi][ni][0], acc[mi][ni][1]);
                *(float2*)(Cf + o1) = make_float2(acc[mi][ni][2], acc[mi][ni][3]);
            } else {
                #pragma unroll
                for (int h = 0; h < 2; h++) {
                    const size_t o = h ? o1 : o0;
                    float x0 = acc[mi][ni][2*h], x1 = acc[mi][ni][2*h+1];
                    __nv_bfloat16 h0 = __float2bfloat16(x0);
                    __nv_bfloat16 h1 = __float2bfloat16(x1);
                    __nv_bfloat16 l0 = __float2bfloat16(x0 - __bfloat162float(h0));
                    __nv_bfloat16 l1 = __float2bfloat16(x1 - __bfloat162float(h1));
                    __nv_bfloat162 hp; hp.x = h0; hp.y = h1;
                    __nv_bfloat162 lp; lp.x = l0; lp.y = l1;
                    *(__nv_bfloat162*)(Chi + o) = hp;
                    *(__nv_bfloat162*)(Clo + o) = lp;
                }
            }
        }
}

// ================= fp16 GEMM3 (NN, single product): out = Eh @ qh =================
static constexpr int STAGE3 = 2 * MATB;    // Eh 16KB + B 16KB = 32KB
static constexpr int SMEM3  = 3 * STAGE3;  // 96KB

__global__ void __launch_bounds__(512, 1)
gemm_f16(const __half* __restrict__ Ahi, const __half* __restrict__ Bq,
         float* __restrict__ Cf)
{
    extern __shared__ char smem[];
    const uint32_t sbase = smem_u32(smem);
    const int tid = threadIdx.x, lane = tid & 31, wid = tid >> 5;
    const int wm = wid >> 2, wn = wid & 3;
    const int b = blockIdx.z, m0 = blockIdx.y * 128, n0 = blockIdx.x * 128;

    const char* gA = (const char*)(Ahi + (size_t)b * TT + (size_t)m0 * 1024);
    const char* gB = (const char*)(Bq + (size_t)b * TT) + (size_t)n0 * 2;

    const int crow[2] = { tid >> 3, (tid + 512) >> 3 };
    const int ccol = tid & 7;
    const int brow[2] = { tid >> 4, (tid + 512) >> 4 };
    const int bcol = tid & 15;

    auto issue_stage = [&](int buf, int kt) {
        const uint32_t sb = sbase + buf * STAGE3;
        const size_t kb = (size_t)kt * 128;
        {
            #pragma unroll
            for (int t = 0; t < 2; t++) {
                const int r = crow[t];
                cp16(sb + r * 128 + ((ccol ^ (r & 7)) * 16),
                     gA + (size_t)r * 2048 + kb + ccol * 16);
            }
        }
        {
            const uint32_t mb = sb + MATB;
            #pragma unroll
            for (int t = 0; t < 2; t++) {
                const int r = brow[t];
                cp16(mb + r * 256 + ((bcol ^ (r & 7)) * 16),
                     gB + (size_t)(kt * 64 + r) * 2048 + bcol * 16);
            }
        }
        cp_commit();
    };

    float acc[2][4][4];
    #pragma unroll
    for (int i = 0; i < 2; i++)
        #pragma unroll
        for (int j = 0; j < 4; j++)
            #pragma unroll
            for (int t = 0; t < 4; t++) acc[i][j][t] = 0.f;

    issue_stage(0, 0);
    issue_stage(1, 1);

    const int lrow = lane & 15, lhi = lane >> 4;
    const int swz = lrow & 7;
    uint32_t koff[4];
    #pragma unroll
    for (int ks = 0; ks < 4; ks++) koff[ks] = (uint32_t)(((ks * 2 + lhi) ^ swz) * 16);

    const uint32_t arow_off = (uint32_t)(wm * 32 + lrow) * 128;

    uint32_t tb_base[2];
    #pragma unroll
    for (int nj = 0; nj < 2; nj++) {
        const int cn = wn * 4 + nj * 2 + lhi;
        tb_base[nj] = (uint32_t)(lrow * 256 + ((cn ^ swz) * 16));
    }

    #pragma unroll 1
    for (int i = 0; i < 16; i++) {
        if (i < 15) cp_wait<1>(); else cp_wait<0>();
        __syncthreads();
        if (i + 2 < 16) issue_stage((i + 2) % 3, i + 2);

        const uint32_t sb = sbase + (i % 3) * STAGE3;
        const uint32_t sA_ = sb, sB_ = sb + MATB;

        #pragma unroll
        for (int ks = 0; ks < 4; ks++) {
            const uint32_t kb = koff[ks];
            uint32_t ah[2][4];
            #pragma unroll
            for (int mi = 0; mi < 2; mi++)
                ldsm4(ah[mi], sA_ + arow_off + (uint32_t)(mi * 16) * 128 + kb);
            uint32_t bq[4][2];
            #pragma unroll
            for (int nj = 0; nj < 2; nj++) {
                const uint32_t ro = (uint32_t)(ks * 4096) + tb_base[nj];
                uint32_t r[4];
                ldsm4t(r, sB_ + ro);
                bq[2*nj][0] = r[0]; bq[2*nj][1] = r[1];
                bq[2*nj+1][0] = r[2]; bq[2*nj+1][1] = r[3];
            }
            #pragma unroll
            for (int mi = 0; mi < 2; mi++)
                #pragma unroll
                for (int ni = 0; ni < 4; ni++)
                    mma16816h(acc[mi][ni], ah[mi], bq[ni][0], bq[ni][1]);
        }
    }

    const int er = m0 + wm * 32 + (lane >> 2);
    const int ec = n0 + wn * 32 + (lane & 3) * 2;
    #pragma unroll
    for (int mi = 0; mi < 2; mi++)
        #pragma unroll
        for (int ni = 0; ni < 4; ni++) {
            const int r0 = er + mi * 16, c = ec + ni * 8;
            const size_t o0 = (size_t)b * TT + (size_t)r0 * 1024 + c;
            *(float2*)(Cf + o0)            = make_float2(acc[mi][ni][0], acc[mi][ni][1]);
            *(float2*)(Cf + o0 + 8 * 1024) = make_float2(acc[mi][ni][2], acc[mi][ni][3]);
        }
}

// ---------------- elementwise / transpose / softmax ----------------
struct alignas(8) bh4 { __nv_bfloat16 a, b, c, d; };

__device__ __forceinline__ void split1(float x, __nv_bfloat16& h, __nv_bfloat16& l) {
    h = __float2bfloat16(x);
    l = __float2bfloat16(x - __bfloat162float(h));
}

__global__ void __launch_bounds__(256)
split2_kernel(const float* __restrict__ X, __nv_bfloat16* __restrict__ hi,
              __nv_bfloat16* __restrict__ lo)
{
    size_t i = (size_t)blockIdx.x * 256 + threadIdx.x;
    float4 v = ((const float4*)X)[i];
    bh4 h, l;
    split1(v.x, h.a, l.a); split1(v.y, h.b, l.b);
    split1(v.z, h.c, l.c); split1(v.w, h.d, l.d);
    ((bh4*)hi)[i] = h;
    ((bh4*)lo)[i] = l;
}

// q prep: straight fp16 plane (GEMM3 B) + transposed bf16 hi/lo (GEMM2 B)
__global__ void __launch_bounds__(256)
splitT_kernel(const float* __restrict__ in, __half* __restrict__ oh16,
              __nv_bfloat16* __restrict__ thi, __nv_bfloat16* __restrict__ tlo)
{
    __shared__ float t[32][33];
    const int b = blockIdx.z;
    const float* I = in + (size_t)b * TT;
    const int x = blockIdx.x * 32 + threadIdx.x;
    const int y = blockIdx.y * 32 + threadIdx.y;
    const size_t ob = (size_t)b * TT;
    #pragma unroll
    for (int j = 0; j < 32; j += 8) {
        float v = I[(size_t)(y + j) * 1024 + x];
        t[threadIdx.y + j][threadIdx.x] = v;
        oh16[ob + (size_t)(y + j) * 1024 + x] = __float2half(v);
    }
    __syncthreads();
    const int ox = blockIdx.y * 32 + threadIdx.x;
    const int oy = blockIdx.x * 32 + threadIdx.y;
    #pragma unroll
    for (int j = 0; j < 32; j += 8) {
        float v = t[threadIdx.x][threadIdx.y + j];
        __nv_bfloat16 h, l; split1(v, h, l);
        thi[ob + (size_t)(oy + j) * 1024 + ox] = h;
        tlo[ob + (size_t)(oy + j) * 1024 + ox] = l;
    }
}

// Fused column softmax (over Tp = rows of S[b]) + exp -> single fp16 plane.
__global__ void __launch_bounds__(256)
softmax_exp_f16(const float* __restrict__ S, __half* __restrict__ Eh)
{
    __shared__ float sm[8][32], sz[8][32];
    __shared__ float fm[32], fz[32];
    const int b = blockIdx.y;
    const int c = (threadIdx.x & 31);
    const int g = threadIdx.x >> 5;
    const int col = blockIdx.x * 32 + c;
    const float* Sb = S + (size_t)b * TT + col;

    float m = -1e30f, z = 0.f;
    #pragma unroll 4
    for (int r = g; r < 1024; r += 8) {
        float x = Sb[(size_t)r << 10];
        if (x > m) { z = z * __expf(m - x) + 1.f; m = x; }
        else       { z += __expf(x - m); }
    }
    sm[g][c] = m; sz[g][c] = z;
    __syncthreads();
    if (threadIdx.x < 32) {
        float M = sm[0][c];
        #pragma unroll
        for (int i = 1; i < 8; i++) M = fmaxf(M, sm[i][c]);
        float Z = 0.f;
        #pragma unroll
        for (int i = 0; i < 8; i++) Z += sz[i][c] * __expf(sm[i][c] - M);
        fm[c] = M; fz[c] = 1.0f / Z;
    }
    __syncthreads();
    const float Mf = fm[c], Rf = fz[c];
    __half* eh = Eh + (size_t)b * TT + col;
    #pragma unroll 4
    for (int r = g; r < 1024; r += 8) {
        float x = Sb[(size_t)r << 10];
        float w = __expf(x - Mf) * Rf;
        eh[(size_t)r << 10] = __float2half(w);
    }
}

// ---------------- launcher ----------------
extern "C" void kernel_launch(void* const* d_in, const int* in_sizes, int n_in,
                              void* d_out, int out_size)
{
    const float* q = (const float*)d_in[0];
    const float* p = (const float*)d_in[1];
    const float* W = (const float*)d_in[2];
    float* out = (float*)d_out;

    __nv_bfloat16 *qThi, *qTlo, *phi, *plo, *Whi, *Wlo, *pWhi, *pWlo;
    __half *qh16, *Eh;
    float *S;
    cudaGetSymbolAddress((void**)&qThi, g_qThi); cudaGetSymbolAddress((void**)&qTlo, g_qTlo);
    cudaGetSymbolAddress((void**)&qh16, g_qh16);
    cudaGetSymbolAddress((void**)&phi, g_phi);   cudaGetSymbolAddress((void**)&plo, g_plo);
    cudaGetSymbolAddress((void**)&Whi, g_Whi);   cudaGetSymbolAddress((void**)&Wlo, g_Wlo);
    cudaGetSymbolAddress((void**)&pWhi, g_pWhi); cudaGetSymbolAddress((void**)&pWlo, g_pWlo);
    cudaGetSymbolAddress((void**)&Eh, g_Eh);
    cudaGetSymbolAddress((void**)&S, g_S);

    cudaFuncSetAttribute(gemm_mma<0>, cudaFuncAttributeMaxDynamicSharedMemorySize, SMEMSZ);
    cudaFuncSetAttribute(gemm_mma<1>, cudaFuncAttributeMaxDynamicSharedMemorySize, SMEMSZ);
    cudaFuncSetAttribute(gemm_f16,    cudaFuncAttributeMaxDynamicSharedMemorySize, SMEM3);

    const dim3 ggrid(8, 8, 16);

    split2_kernel<<<16384, 256>>>(p, phi, plo);
    splitT_kernel<<<dim3(32, 32, 16), dim3(32, 8)>>>(q, qh16, qThi, qTlo);
    split2_kernel<<<1024,  256>>>(W, Whi, Wlo);

    // GEMM1 (NN bf16): pW = p @ W, split-store
    gemm_mma<1><<<ggrid, 512, SMEMSZ>>>(phi, plo, TT, Whi, Wlo, 0L,
                                        nullptr, pWhi, pWlo);
    // GEMM2 (NN bf16): S = pW @ q^T (B = qT k-row-major) -> fp32
    gemm_mma<0><<<ggrid, 512, SMEMSZ>>>(pWhi, pWlo, TT, qThi, qTlo, TT,
                                        S, nullptr, nullptr);
    // softmax over Tp + exp -> fp16 plane
    softmax_exp_f16<<<dim3(32, 16), 256>>>(S, Eh);
    // GEMM3 (NN fp16, single product): out = Eh @ qh
    gemm_f16<<<ggrid, 512, SMEM3>>>(Eh, qh16, out);
}

// round 15
// speedup vs baseline: 2.2284x; 1.0261x over previous
#include <cuda_runtime.h>
#include <cuda_bf16.h>
#include <cuda_fp16.h>
#include <cstdint>

// B=16, TQ=TP=DQ=DP=1024
// out = softmax_over_Tp((p@W)@q^T) @ q, fp32 in/out.
// GEMM1/2: bf16 mma.sync 2-way split, 3 products (NN via ldmatrix.trans).
//   GEMM2 epilogue emits per-CTA column softmax partials (m, sumexp).
// GEMM3:   fp16 mma.sync single product Eh @ qh, K-chunk 128.

static const long TT = 1048576L;

// ---------------- scratch ----------------
__device__ __nv_bfloat16 g_qThi[16777216], g_qTlo[16777216];
__device__ __half        g_qh16[16777216];
__device__ __nv_bfloat16 g_phi[16777216], g_plo[16777216];
__device__ __nv_bfloat16 g_Whi[1048576],  g_Wlo[1048576];
__device__ __nv_bfloat16 g_pWhi[16777216], g_pWlo[16777216];
__device__ __half        g_Eh[16777216];
__device__ float g_S[16777216];
__device__ float2 g_part[16 * 8 * 1024];   // per (b, mtile, col) partial (m, z)
__device__ float g_M[16384], g_R[16384];   // final per-column max, 1/Z

// ---------------- asm helpers ----------------
__device__ __forceinline__ uint32_t smem_u32(const void* p) {
    uint32_t a;
    asm("{ .reg .u64 t; cvta.to.shared.u64 t, %1; cvt.u32.u64 %0, t; }" : "=r"(a) : "l"(p));
    return a;
}
__device__ __forceinline__ void cp16(uint32_t s, const void* g) {
    asm volatile("cp.async.cg.shared.global [%0], [%1], 16;" :: "r"(s), "l"(g));
}
__device__ __forceinline__ void cp_commit() { asm volatile("cp.async.commit_group;"); }
template<int N>
__device__ __forceinline__ void cp_wait() { asm volatile("cp.async.wait_group %0;" :: "n"(N)); }

__device__ __forceinline__ void ldsm4(uint32_t (&r)[4], uint32_t a) {
    asm volatile("ldmatrix.sync.aligned.m8n8.x4.shared.b16 {%0,%1,%2,%3}, [%4];"
                 : "=r"(r[0]), "=r"(r[1]), "=r"(r[2]), "=r"(r[3]) : "r"(a));
}
__device__ __forceinline__ void ldsm4t(uint32_t (&r)[4], uint32_t a) {
    asm volatile("ldmatrix.sync.aligned.m8n8.x4.trans.shared.b16 {%0,%1,%2,%3}, [%4];"
                 : "=r"(r[0]), "=r"(r[1]), "=r"(r[2]), "=r"(r[3]) : "r"(a));
}
__device__ __forceinline__ void mma16816(float (&d)[4], const uint32_t (&a)[4],
                                         uint32_t b0, uint32_t b1) {
    asm volatile(
        "mma.sync.aligned.m16n8k16.row.col.f32.bf16.bf16.f32 "
        "{%0,%1,%2,%3}, {%4,%5,%6,%7}, {%8,%9}, {%0,%1,%2,%3};"
        : "+f"(d[0]), "+f"(d[1]), "+f"(d[2]), "+f"(d[3])
        : "r"(a[0]), "r"(a[1]), "r"(a[2]), "r"(a[3]), "r"(b0), "r"(b1));
}
__device__ __forceinline__ void mma16816h(float (&d)[4], const uint32_t (&a)[4],
                                          uint32_t b0, uint32_t b1) {
    asm volatile(
        "mma.sync.aligned.m16n8k16.row.col.f32.f16.f16.f32 "
        "{%0,%1,%2,%3}, {%4,%5,%6,%7}, {%8,%9}, {%0,%1,%2,%3};"
        : "+f"(d[0]), "+f"(d[1]), "+f"(d[2]), "+f"(d[3])
        : "r"(a[0]), "r"(a[1]), "r"(a[2]), "r"(a[3]), "r"(b0), "r"(b1));
}

// ================= bf16 GEMM (NN): C[b][m][n] = sum_k A[b][m][k] * B[b][k][n] =================
static constexpr int MATB   = 128 * 128;
static constexpr int STAGEB = 4 * MATB;
static constexpr int SMEMSZ = 3 * STAGEB;  // 192KB

// STORE_SPLIT=1: split-store bf16 hi/lo.  STORE_SPLIT=0: store fp32 + column softmax partials.
template<int STORE_SPLIT>
__global__ void __launch_bounds__(512, 1)
gemm_mma(const __nv_bfloat16* __restrict__ Ahi, const __nv_bfloat16* __restrict__ Alo, long sA,
         const __nv_bfloat16* __restrict__ Bhi, const __nv_bfloat16* __restrict__ Blo, long sB,
         float* __restrict__ Cf, __nv_bfloat16* __restrict__ Chi, __nv_bfloat16* __restrict__ Clo,
         float2* __restrict__ gPart)
{
    extern __shared__ char smem[];
    const uint32_t sbase = smem_u32(smem);
    const int tid = threadIdx.x, lane = tid & 31, wid = tid >> 5;
    const int wm = wid >> 2, wn = wid & 3;
    const int b = blockIdx.z, m0 = blockIdx.y * 128, n0 = blockIdx.x * 128;

    const char* gA[2] = { (const char*)(Ahi + (size_t)b * sA + (size_t)m0 * 1024),
                          (const char*)(Alo + (size_t)b * sA + (size_t)m0 * 1024) };
    const char* gB[2] = { (const char*)(Bhi + (size_t)b * sB) + (size_t)n0 * 2,
                          (const char*)(Blo + (size_t)b * sB) + (size_t)n0 * 2 };

    const int crow[2] = { tid >> 3, (tid + 512) >> 3 };
    const int ccol = tid & 7;
    const int brow[2] = { tid >> 4, (tid + 512) >> 4 };
    const int bcol = tid & 15;

    auto issue_stage = [&](int buf, int kt) {
        const uint32_t sb = sbase + buf * STAGEB;
        const size_t kb = (size_t)kt * 128;
        #pragma unroll
        for (int m = 0; m < 2; m++) {
            const uint32_t mb = sb + m * MATB;
            #pragma unroll
            for (int t = 0; t < 2; t++) {
                const int r = crow[t];
                cp16(mb + r * 128 + ((ccol ^ (r & 7)) * 16),
                     gA[m] + (size_t)r * 2048 + kb + ccol * 16);
            }
        }
        #pragma unroll
        for (int m = 0; m < 2; m++) {
            const uint32_t mb = sb + (2 + m) * MATB;
            #pragma unroll
            for (int t = 0; t < 2; t++) {
                const int r = brow[t];
                cp16(mb + r * 256 + ((bcol ^ (r & 7)) * 16),
                     gB[m] + (size_t)(kt * 64 + r) * 2048 + bcol * 16);
            }
        }
        cp_commit();
    };

    float acc[2][4][4];
    #pragma unroll
    for (int i = 0; i < 2; i++)
        #pragma unroll
        for (int j = 0; j < 4; j++)
            #pragma unroll
            for (int t = 0; t < 4; t++) acc[i][j][t] = 0.f;

    issue_stage(0, 0);
    issue_stage(1, 1);

    const int lrow = lane & 15, lhi = lane >> 4;
    const int swz = lrow & 7;
    uint32_t koff[4];
    #pragma unroll
    for (int ks = 0; ks < 4; ks++) koff[ks] = (uint32_t)(((ks * 2 + lhi) ^ swz) * 16);

    const uint32_t arow_off = (uint32_t)(wm * 32 + lrow) * 128;

    uint32_t tb_base[2];
    #pragma unroll
    for (int nj = 0; nj < 2; nj++) {
        const int cn = wn * 4 + nj * 2 + lhi;
        tb_base[nj] = (uint32_t)(lrow * 256 + ((cn ^ swz) * 16));
    }

    #pragma unroll 1
    for (int i = 0; i < 16; i++) {
        if (i < 15) cp_wait<1>(); else cp_wait<0>();
        __syncthreads();
        if (i + 2 < 16) issue_stage((i + 2) % 3, i + 2);

        const uint32_t sb = sbase + (i % 3) * STAGEB;
        const uint32_t sAh = sb, sAl = sb + MATB, sBh = sb + 2 * MATB, sBl = sb + 3 * MATB;

        #pragma unroll
        for (int ks = 0; ks < 4; ks++) {
            const uint32_t kb = koff[ks];
            uint32_t ah[2][4], al[2][4];
            #pragma unroll
            for (int mi = 0; mi < 2; mi++) {
                const uint32_t ro = arow_off + (uint32_t)(mi * 16) * 128 + kb;
                ldsm4(ah[mi], sAh + ro);
                ldsm4(al[mi], sAl + ro);
            }
            uint32_t bh[4][2], bl[4][2];
            #pragma unroll
            for (int nj = 0; nj < 2; nj++) {
                const uint32_t ro = (uint32_t)(ks * 4096) + tb_base[nj];
                uint32_t r[4];
                ldsm4t(r, sBh + ro);
                bh[2*nj][0] = r[0]; bh[2*nj][1] = r[1];
                bh[2*nj+1][0] = r[2]; bh[2*nj+1][1] = r[3];
                ldsm4t(r, sBl + ro);
                bl[2*nj][0] = r[0]; bl[2*nj][1] = r[1];
                bl[2*nj+1][0] = r[2]; bl[2*nj+1][1] = r[3];
            }
            #pragma unroll
            for (int mi = 0; mi < 2; mi++)
                #pragma unroll
                for (int ni = 0; ni < 4; ni++) {
                    mma16816(acc[mi][ni], ah[mi], bh[ni][0], bh[ni][1]);
                    mma16816(acc[mi][ni], ah[mi], bl[ni][0], bl[ni][1]);
                    mma16816(acc[mi][ni], al[mi], bh[ni][0], bh[ni][1]);
                }
        }
    }

    // ---------------- epilogue ----------------
    const int er = m0 + wm * 32 + (lane >> 2);
    const int ec = n0 + wn * 32 + (lane & 3) * 2;
    #pragma unroll
    for (int mi = 0; mi < 2; mi++)
        #pragma unroll
        for (int ni = 0; ni < 4; ni++) {
            const int r0 = er + mi * 16, c = ec + ni * 8;
            const size_t o0 = (size_t)b * TT + (size_t)r0 * 1024 + c;
            const size_t o1 = o0 + 8 * 1024;
            if (STORE_SPLIT == 0) {
                *(float2*)(Cf + o0) = make_float2(acc[mi][ni][0], acc[mi][ni][1]);
                *(float2*)(Cf + o1) = make_float2(acc[mi][ni][2], acc[mi][ni][3]);
            } else {
                #pragma unroll
                for (int h = 0; h < 2; h++) {
                    const size_t o = h ? o1 : o0;
                    float x0 = acc[mi][ni][2*h], x1 = acc[mi][ni][2*h+1];
                    __nv_bfloat16 h0 = __float2bfloat16(x0);
                    __nv_bfloat16 h1 = __float2bfloat16(x1);
                    __nv_bfloat16 l0 = __float2bfloat16(x0 - __bfloat162float(h0));
                    __nv_bfloat16 l1 = __float2bfloat16(x1 - __bfloat162float(h1));
                    __nv_bfloat162 hp; hp.x = h0; hp.y = h1;
                    __nv_bfloat162 lp; lp.x = l0; lp.y = l1;
                    *(__nv_bfloat162*)(Chi + o) = hp;
                    *(__nv_bfloat162*)(Clo + o) = lp;
                }
            }
        }

    if (STORE_SPLIT == 0) {
        // per-CTA column softmax partials over this 128-row tile
        // per thread: 8 columns (ni x pair), 4 row-values each
        float pm[8], pz[8];
        #pragma unroll
        for (int ni = 0; ni < 4; ni++)
            #pragma unroll
            for (int pr = 0; pr < 2; pr++) {
                float v0 = acc[0][ni][pr],   v1 = acc[0][ni][pr+2];
                float v2 = acc[1][ni][pr],   v3 = acc[1][ni][pr+2];
                float m = fmaxf(fmaxf(v0, v1), fmaxf(v2, v3));
                float z = __expf(v0 - m) + __expf(v1 - m) + __expf(v2 - m) + __expf(v3 - m);
                pm[ni * 2 + pr] = m;
                pz[ni * 2 + pr] = z;
            }
        // reduce over the 8 row-lanes (lane>>2) via xor shuffles
        #pragma unroll
        for (int t = 0; t < 8; t++) {
            float m = pm[t], z = pz[t];
            #pragma unroll
            for (int off = 4; off < 32; off <<= 1) {
                float om = __shfl_xor_sync(0xffffffffu, m, off);
                float oz = __shfl_xor_sync(0xffffffffu, z, off);
                float nm = fmaxf(m, om);
                z = z * __expf(m - nm) + oz * __expf(om - nm);
                m = nm;
            }
            pm[t] = m; pz[t] = z;
        }
        __syncthreads();
        float2* part = (float2*)smem;   // [wm][wn][32] = 4KB
        if (lane < 4) {
            #pragma unroll
            for (int ni = 0; ni < 4; ni++)
                #pragma unroll
                for (int pr = 0; pr < 2; pr++) {
                    const int ci = ni * 8 + lane * 2 + pr;
                    part[(wm * 4 + wn) * 32 + ci] = make_float2(pm[ni*2+pr], pz[ni*2+pr]);
                }
        }
        __syncthreads();
        if (tid < 128) {
            const int wnn = tid >> 5, ci = tid & 31;
            float m = -1e30f, z = 0.f;
            #pragma unroll
            for (int w = 0; w < 4; w++) {
                float2 pv = part[(w * 4 + wnn) * 32 + ci];
                float nm = fmaxf(m, pv.x);
                z = z * __expf(m - nm) + pv.y * __expf(pv.x - nm);
                m = nm;
            }
            const int cg = n0 + wnn * 32 + ci;
            gPart[((size_t)b * 8 + blockIdx.y) * 1024 + cg] = make_float2(m, z);
        }
    }
}

// ================= fp16 GEMM3 (NN, single product, K-chunk 128): out = Eh @ qh =================
static constexpr int MAT3   = 128 * 256;   // 32KB plane (128 rows x 256B)
static constexpr int STAGE3 = 2 * MAT3;    // 64KB
static constexpr int SMEM3  = 3 * STAGE3;  // 192KB

__global__ void __launch_bounds__(512, 1)
gemm_f16(const __half* __restrict__ Ahi, const __half* __restrict__ Bq,
         float* __restrict__ Cf)
{
    extern __shared__ char smem[];
    const uint32_t sbase = smem_u32(smem);
    const int tid = threadIdx.x, lane = tid & 31, wid = tid >> 5;
    const int wm = wid >> 2, wn = wid & 3;
    const int b = blockIdx.z, m0 = blockIdx.y * 128, n0 = blockIdx.x * 128;

    const char* gA = (const char*)(Ahi + (size_t)b * TT + (size_t)m0 * 1024);
    const char* gB = (const char*)(Bq + (size_t)b * TT) + (size_t)n0 * 2;

    // loaders: each plane 128 rows x 16 chunks (2048 chunks), thread does 4
    const int crow4[4] = { tid >> 4, (tid + 512) >> 4, (tid + 1024) >> 4, (tid + 1536) >> 4 };
    const int ccol = tid & 15;

    auto issue_stage = [&](int buf, int kt) {
        const uint32_t sb = sbase + buf * STAGE3;
        const size_t kb = (size_t)kt * 256;   // 128 fp16 = 256B within 2048B row
        #pragma unroll
        for (int t = 0; t < 4; t++) {
            const int r = crow4[t];
            cp16(sb + r * 256 + ((ccol ^ (r & 7)) * 16),
                 gA + (size_t)r * 2048 + kb + ccol * 16);
        }
        const uint32_t mb = sb + MAT3;
        #pragma unroll
        for (int t = 0; t < 4; t++) {
            const int r = crow4[t];
            cp16(mb + r * 256 + ((ccol ^ (r & 7)) * 16),
                 gB + (size_t)(kt * 128 + r) * 2048 + ccol * 16);
        }
        cp_commit();
    };

    float acc[2][4][4];
    #pragma unroll
    for (int i = 0; i < 2; i++)
        #pragma unroll
        for (int j = 0; j < 4; j++)
            #pragma unroll
            for (int t = 0; t < 4; t++) acc[i][j][t] = 0.f;

    issue_stage(0, 0);
    issue_stage(1, 1);

    const int lrow = lane & 15, lhi = lane >> 4;
    const int swz = lrow & 7;
    uint32_t koff[8];
    #pragma unroll
    for (int ks = 0; ks < 8; ks++) koff[ks] = (uint32_t)(((ks * 2 + lhi) ^ swz) * 16);

    const uint32_t arow_off = (uint32_t)(wm * 32 + lrow) * 256;

    uint32_t tb_base[2];
    #pragma unroll
    for (int nj = 0; nj < 2; nj++) {
        const int cn = wn * 4 + nj * 2 + lhi;
        tb_base[nj] = (uint32_t)(lrow * 256 + ((cn ^ swz) * 16));
    }

    #pragma unroll 1
    for (int i = 0; i < 8; i++) {
        if (i < 7) cp_wait<1>(); else cp_wait<0>();
        __syncthreads();
        if (i + 2 < 8) issue_stage((i + 2) % 3, i + 2);

        const uint32_t sb = sbase + (i % 3) * STAGE3;
        const uint32_t sA_ = sb, sB_ = sb + MAT3;

        #pragma unroll
        for (int ks = 0; ks < 8; ks++) {
            const uint32_t kb = koff[ks];
            uint32_t ah[2][4];
            #pragma unroll
            for (int mi = 0; mi < 2; mi++)
                ldsm4(ah[mi], sA_ + arow_off + (uint32_t)(mi * 16) * 256 + kb);
            uint32_t bq[4][2];
            #pragma unroll
            for (int nj = 0; nj < 2; nj++) {
                const uint32_t ro = (uint32_t)(ks * 4096) + tb_base[nj];
                uint32_t r[4];
                ldsm4t(r, sB_ + ro);
                bq[2*nj][0] = r[0]; bq[2*nj][1] = r[1];
                bq[2*nj+1][0] = r[2]; bq[2*nj+1][1] = r[3];
            }
            #pragma unroll
            for (int mi = 0; mi < 2; mi++)
                #pragma unroll
                for (int ni = 0; ni < 4; ni++)
                    mma16816h(acc[mi][ni], ah[mi], bq[ni][0], bq[ni][1]);
        }
    }

    const int er = m0 + wm * 32 + (lane >> 2);
    const int ec = n0 + wn * 32 + (lane & 3) * 2;
    #pragma unroll
    for (int mi = 0; mi < 2; mi++)
        #pragma unroll
        for (int ni = 0; ni < 4; ni++) {
            const int r0 = er + mi * 16, c = ec + ni * 8;
            const size_t o0 = (size_t)b * TT + (size_t)r0 * 1024 + c;
            *(float2*)(Cf + o0)            = make_float2(acc[mi][ni][0], acc[mi][ni][1]);
            *(float2*)(Cf + o0 + 8 * 1024) = make_float2(acc[mi][ni][2], acc[mi][ni][3]);
        }
}

// ---------------- elementwise / transpose / softmax ----------------
struct alignas(8) bh4 { __nv_bfloat16 a, b, c, d; };

__device__ __forceinline__ void split1(float x, __nv_bfloat16& h, __nv_bfloat16& l) {
    h = __float2bfloat16(x);
    l = __float2bfloat16(x - __bfloat162float(h));
}

__global__ void __launch_bounds__(256)
split2_kernel(const float* __restrict__ X, __nv_bfloat16* __restrict__ hi,
              __nv_bfloat16* __restrict__ lo)
{
    size_t i = (size_t)blockIdx.x * 256 + threadIdx.x;
    float4 v = ((const float4*)X)[i];
    bh4 h, l;
    split1(v.x, h.a, l.a); split1(v.y, h.b, l.b);
    split1(v.z, h.c, l.c); split1(v.w, h.d, l.d);
    ((bh4*)hi)[i] = h;
    ((bh4*)lo)[i] = l;
}

// q prep: straight fp16 plane (GEMM3 B) + transposed bf16 hi/lo (GEMM2 B)
__global__ void __launch_bounds__(256)
splitT_kernel(const float* __restrict__ in, __half* __restrict__ oh16,
              __nv_bfloat16* __restrict__ thi, __nv_bfloat16* __restrict__ tlo)
{
    __shared__ float t[32][33];
    const int b = blockIdx.z;
    const float* I = in + (size_t)b * TT;
    const int x = blockIdx.x * 32 + threadIdx.x;
    const int y = blockIdx.y * 32 + threadIdx.y;
    const size_t ob = (size_t)b * TT;
    #pragma unroll
    for (int j = 0; j < 32; j += 8) {
        float v = I[(size_t)(y + j) * 1024 + x];
        t[threadIdx.y + j][threadIdx.x] = v;
        oh16[ob + (size_t)(y + j) * 1024 + x] = __float2half(v);
    }
    __syncthreads();
    const int ox = blockIdx.y * 32 + threadIdx.x;
    const int oy = blockIdx.x * 32 + threadIdx.y;
    #pragma unroll
    for (int j = 0; j < 32; j += 8) {
        float v = t[threadIdx.x][threadIdx.y + j];
        __nv_bfloat16 h, l; split1(v, h, l);
        thi[ob + (size_t)(oy + j) * 1024 + ox] = h;
        tlo[ob + (size_t)(oy + j) * 1024 + ox] = l;
    }
}

// combine per-mtile partials -> final (M, 1/Z) per column
__global__ void __launch_bounds__(256)
combine_stats(const float2* __restrict__ gPart,
              float* __restrict__ gM, float* __restrict__ gR)
{
    const int idx = blockIdx.x * 256 + threadIdx.x;   // b*1024 + col
    const int b = idx >> 10, col = idx & 1023;
    float m = -1e30f, z = 0.f;
    #pragma unroll
    for (int t = 0; t < 8; t++) {
        float2 pv = gPart[((size_t)b * 8 + t) * 1024 + col];
        float nm = fmaxf(m, pv.x);
        z = z * __expf(m - nm) + pv.y * __expf(pv.x - nm);
        m = nm;
    }
    gM[idx] = m;
    gR[idx] = 1.0f / z;
}

// exp pass: single read of S -> fp16 E plane
__global__ void __launch_bounds__(256)
exp_f16(const float* __restrict__ S, const float* __restrict__ gM,
        const float* __restrict__ gR, __half* __restrict__ Eh)
{
    const int b = blockIdx.y;
    const int c = (threadIdx.x & 31);
    const int g = threadIdx.x >> 5;
    const int col = blockIdx.x * 32 + c;
    const float Mf = gM[b * 1024 + col];
    const float Rf = gR[b * 1024 + col];
    const float* Sb = S + (size_t)b * TT + col;
    __half* eh = Eh + (size_t)b * TT + col;
    #pragma unroll 4
    for (int r = g; r < 1024; r += 8) {
        float x = Sb[(size_t)r << 10];
        eh[(size_t)r << 10] = __float2half(__expf(x - Mf) * Rf);
    }
}

// ---------------- launcher ----------------
extern "C" void kernel_launch(void* const* d_in, const int* in_sizes, int n_in,
                              void* d_out, int out_size)
{
    const float* q = (const float*)d_in[0];
    const float* p = (const float*)d_in[1];
    const float* W = (const float*)d_in[2];
    float* out = (float*)d_out;

    __nv_bfloat16 *qThi, *qTlo, *phi, *plo, *Whi, *Wlo, *pWhi, *pWlo;
    __half *qh16, *Eh;
    float *S, *gM, *gR;
    float2 *gPart;
    cudaGetSymbolAddress((void**)&qThi, g_qThi); cudaGetSymbolAddress((void**)&qTlo, g_qTlo);
    cudaGetSymbolAddress((void**)&qh16, g_qh16);
    cudaGetSymbolAddress((void**)&phi, g_phi);   cudaGetSymbolAddress((void**)&plo, g_plo);
    cudaGetSymbolAddress((void**)&Whi, g_Whi);   cudaGetSymbolAddress((void**)&Wlo, g_Wlo);
    cudaGetSymbolAddress((void**)&pWhi, g_pWhi); cudaGetSymbolAddress((void**)&pWlo, g_pWlo);
    cudaGetSymbolAddress((void**)&Eh, g_Eh);
    cudaGetSymbolAddress((void**)&S, g_S);
    cudaGetSymbolAddress((void**)&gPart, g_part);
    cudaGetSymbolAddress((void**)&gM, g_M);      cudaGetSymbolAddress((void**)&gR, g_R);

    cudaFuncSetAttribute(gemm_mma<0>, cudaFuncAttributeMaxDynamicSharedMemorySize, SMEMSZ);
    cudaFuncSetAttribute(gemm_mma<1>, cudaFuncAttributeMaxDynamicSharedMemorySize, SMEMSZ);
    cudaFuncSetAttribute(gemm_f16,    cudaFuncAttributeMaxDynamicSharedMemorySize, SMEM3);

    const dim3 ggrid(8, 8, 16);

    split2_kernel<<<16384, 256>>>(p, phi, plo);
    splitT_kernel<<<dim3(32, 32, 16), dim3(32, 8)>>>(q, qh16, qThi, qTlo);
    split2_kernel<<<1024,  256>>>(W, Whi, Wlo);

    // GEMM1 (NN bf16): pW = p @ W, split-store
    gemm_mma<1><<<ggrid, 512, SMEMSZ>>>(phi, plo, TT, Whi, Wlo, 0L,
                                        nullptr, pWhi, pWlo, nullptr);
    // GEMM2 (NN bf16): S = pW @ q^T -> fp32 + column softmax partials
    gemm_mma<0><<<ggrid, 512, SMEMSZ>>>(pWhi, pWlo, TT, qThi, qTlo, TT,
                                        S, nullptr, nullptr, gPart);
    // combine partials -> final column stats
    combine_stats<<<64, 256>>>(gPart, gM, gR);
    // exp: single read of S -> fp16 E
    exp_f16<<<dim3(32, 16), 256>>>(S, gM, gR, Eh);
    // GEMM3 (NN fp16, single product, K128): out = Eh @ qh
    gemm_f16<<<ggrid, 512, SMEM3>>>(Eh, qh16, out);
}

// round 17
// speedup vs baseline: 2.2313x; 1.0013x over previous
#include <cuda_runtime.h>
#include <cuda_bf16.h>
#include <cuda_fp16.h>
#include <cstdint>

// B=16, TQ=TP=DQ=DP=1024
// out = softmax_over_Tp((p@W)@q^T) @ q, fp32 in/out.
// GEMM1: bf16 mma 3 products (NN), epilogue splits pW into fp16 hi/lo.
// GEMM2: fp16 mma 3 products (pWh,pWl)@(qTh,qTl), epilogue emits softmax partials.
// GEMM3: fp16 mma single product Eh @ qh, CTA tile 128x256.

static const long TT = 1048576L;

// ---------------- scratch ----------------
__device__ __half        g_qThi[16777216], g_qTlo[16777216];  // q^T fp16 planes (GEMM2 B)
__device__ __half        g_qh16[16777216];                    // q fp16 (GEMM3 B)
__device__ __nv_bfloat16 g_phi[16777216], g_plo[16777216];
__device__ __nv_bfloat16 g_Whi[1048576],  g_Wlo[1048576];
__device__ __half        g_pWhi[16777216], g_pWlo[16777216];
__device__ __half        g_Eh[16777216];
__device__ float g_S[16777216];
__device__ float2 g_part[16 * 8 * 1024];
__device__ float g_M[16384], g_R[16384];

// ---------------- asm helpers ----------------
__device__ __forceinline__ uint32_t smem_u32(const void* p) {
    uint32_t a;
    asm("{ .reg .u64 t; cvta.to.shared.u64 t, %1; cvt.u32.u64 %0, t; }" : "=r"(a) : "l"(p));
    return a;
}
__device__ __forceinline__ void cp16(uint32_t s, const void* g) {
    asm volatile("cp.async.cg.shared.global [%0], [%1], 16;" :: "r"(s), "l"(g));
}
__device__ __forceinline__ void cp_commit() { asm volatile("cp.async.commit_group;"); }
template<int N>
__device__ __forceinline__ void cp_wait() { asm volatile("cp.async.wait_group %0;" :: "n"(N)); }

__device__ __forceinline__ void ldsm4(uint32_t (&r)[4], uint32_t a) {
    asm volatile("ldmatrix.sync.aligned.m8n8.x4.shared.b16 {%0,%1,%2,%3}, [%4];"
                 : "=r"(r[0]), "=r"(r[1]), "=r"(r[2]), "=r"(r[3]) : "r"(a));
}
__device__ __forceinline__ void ldsm4t(uint32_t (&r)[4], uint32_t a) {
    asm volatile("ldmatrix.sync.aligned.m8n8.x4.trans.shared.b16 {%0,%1,%2,%3}, [%4];"
                 : "=r"(r[0]), "=r"(r[1]), "=r"(r[2]), "=r"(r[3]) : "r"(a));
}
__device__ __forceinline__ void mma16816(float (&d)[4], const uint32_t (&a)[4],
                                         uint32_t b0, uint32_t b1) {
    asm volatile(
        "mma.sync.aligned.m16n8k16.row.col.f32.bf16.bf16.f32 "
        "{%0,%1,%2,%3}, {%4,%5,%6,%7}, {%8,%9}, {%0,%1,%2,%3};"
        : "+f"(d[0]), "+f"(d[1]), "+f"(d[2]), "+f"(d[3])
        : "r"(a[0]), "r"(a[1]), "r"(a[2]), "r"(a[3]), "r"(b0), "r"(b1));
}
__device__ __forceinline__ void mma16816h(float (&d)[4], const uint32_t (&a)[4],
                                          uint32_t b0, uint32_t b1) {
    asm volatile(
        "mma.sync.aligned.m16n8k16.row.col.f32.f16.f16.f32 "
        "{%0,%1,%2,%3}, {%4,%5,%6,%7}, {%8,%9}, {%0,%1,%2,%3};"
        : "+f"(d[0]), "+f"(d[1]), "+f"(d[2]), "+f"(d[3])
        : "r"(a[0]), "r"(a[1]), "r"(a[2]), "r"(a[3]), "r"(b0), "r"(b1));
}

static constexpr int MATB = 128 * 128;   // 16KB (128 rows x 128B)

// ================= GEMM1 (NN bf16, 3 products): pW = p @ W, split-store fp16 =================
static constexpr int STAGE1 = 4 * MATB;    // 64KB
static constexpr int SMEM1  = 3 * STAGE1;  // 192KB

__global__ void __launch_bounds__(512, 1)
gemm1(const __nv_bfloat16* __restrict__ Ahi, const __nv_bfloat16* __restrict__ Alo,
      const __nv_bfloat16* __restrict__ Bhi, const __nv_bfloat16* __restrict__ Blo,
      __half* __restrict__ Chi, __half* __restrict__ Clo)
{
    extern __shared__ char smem[];
    const uint32_t sbase = smem_u32(smem);
    const int tid = threadIdx.x, lane = tid & 31, wid = tid >> 5;
    const int wm = wid >> 2, wn = wid & 3;
    const int b = blockIdx.z, m0 = blockIdx.y * 128, n0 = blockIdx.x * 128;

    const char* gA[2] = { (const char*)(Ahi + (size_t)b * TT + (size_t)m0 * 1024),
                          (const char*)(Alo + (size_t)b * TT + (size_t)m0 * 1024) };
    const char* gB[2] = { (const char*)Bhi + (size_t)n0 * 2,
                          (const char*)Blo + (size_t)n0 * 2 };

    const int crow[2] = { tid >> 3, (tid + 512) >> 3 };
    const int ccol = tid & 7;
    const int brow[2] = { tid >> 4, (tid + 512) >> 4 };
    const int bcol = tid & 15;

    auto issue_stage = [&](int buf, int kt) {
        const uint32_t sb = sbase + buf * STAGE1;
        const size_t kb = (size_t)kt * 128;
        #pragma unroll
        for (int m = 0; m < 2; m++) {
            const uint32_t mb = sb + m * MATB;
            #pragma unroll
            for (int t = 0; t < 2; t++) {
                const int r = crow[t];
                cp16(mb + r * 128 + ((ccol ^ (r & 7)) * 16),
                     gA[m] + (size_t)r * 2048 + kb + ccol * 16);
            }
        }
        #pragma unroll
        for (int m = 0; m < 2; m++) {
            const uint32_t mb = sb + (2 + m) * MATB;
            #pragma unroll
            for (int t = 0; t < 2; t++) {
                const int r = brow[t];
                cp16(mb + r * 256 + ((bcol ^ (r & 7)) * 16),
                     gB[m] + (size_t)(kt * 64 + r) * 2048 + bcol * 16);
            }
        }
        cp_commit();
    };

    float acc[2][4][4];
    #pragma unroll
    for (int i = 0; i < 2; i++)
        #pragma unroll
        for (int j = 0; j < 4; j++)
            #pragma unroll
            for (int t = 0; t < 4; t++) acc[i][j][t] = 0.f;

    issue_stage(0, 0);
    issue_stage(1, 1);

    const int lrow = lane & 15, lhi = lane >> 4;
    const int swz = lrow & 7;
    uint32_t koff[4];
    #pragma unroll
    for (int ks = 0; ks < 4; ks++) koff[ks] = (uint32_t)(((ks * 2 + lhi) ^ swz) * 16);

    const uint32_t arow_off = (uint32_t)(wm * 32 + lrow) * 128;
    uint32_t tb_base[2];
    #pragma unroll
    for (int nj = 0; nj < 2; nj++) {
        const int cn = wn * 4 + nj * 2 + lhi;
        tb_base[nj] = (uint32_t)(lrow * 256 + ((cn ^ swz) * 16));
    }

    #pragma unroll 1
    for (int i = 0; i < 16; i++) {
        if (i < 15) cp_wait<1>(); else cp_wait<0>();
        __syncthreads();
        if (i + 2 < 16) issue_stage((i + 2) % 3, i + 2);

        const uint32_t sb = sbase + (i % 3) * STAGE1;
        const uint32_t sAh = sb, sAl = sb + MATB, sBh = sb + 2 * MATB, sBl = sb + 3 * MATB;

        #pragma unroll
        for (int ks = 0; ks < 4; ks++) {
            const uint32_t kb = koff[ks];
            uint32_t ah[2][4], al[2][4];
            #pragma unroll
            for (int mi = 0; mi < 2; mi++) {
                const uint32_t ro = arow_off + (uint32_t)(mi * 16) * 128 + kb;
                ldsm4(ah[mi], sAh + ro);
                ldsm4(al[mi], sAl + ro);
            }
            uint32_t bh[4][2], bl[4][2];
            #pragma unroll
            for (int nj = 0; nj < 2; nj++) {
                const uint32_t ro = (uint32_t)(ks * 4096) + tb_base[nj];
                uint32_t r[4];
                ldsm4t(r, sBh + ro);
                bh[2*nj][0] = r[0]; bh[2*nj][1] = r[1];
                bh[2*nj+1][0] = r[2]; bh[2*nj+1][1] = r[3];
                ldsm4t(r, sBl + ro);
                bl[2*nj][0] = r[0]; bl[2*nj][1] = r[1];
                bl[2*nj+1][0] = r[2]; bl[2*nj+1][1] = r[3];
            }
            #pragma unroll
            for (int mi = 0; mi < 2; mi++)
                #pragma unroll
                for (int ni = 0; ni < 4; ni++) {
                    mma16816(acc[mi][ni], ah[mi], bh[ni][0], bh[ni][1]);
                    mma16816(acc[mi][ni], ah[mi], bl[ni][0], bl[ni][1]);
                    mma16816(acc[mi][ni], al[mi], bh[ni][0], bh[ni][1]);
                }
        }
    }

    // epilogue: split fp32 -> fp16 hi/lo
    const int er = m0 + wm * 32 + (lane >> 2);
    const int ec = n0 + wn * 32 + (lane & 3) * 2;
    #pragma unroll
    for (int mi = 0; mi < 2; mi++)
        #pragma unroll
        for (int ni = 0; ni < 4; ni++) {
            const int r0 = er + mi * 16, c = ec + ni * 8;
            const size_t o0 = (size_t)b * TT + (size_t)r0 * 1024 + c;
            #pragma unroll
            for (int h = 0; h < 2; h++) {
                const size_t o = h ? (o0 + 8 * 1024) : o0;
                float x0 = acc[mi][ni][h ? 2 : 0];
                float x1 = acc[mi][ni][h ? 3 : 1];
                __half h0 = __float2half(x0);
                __half h1 = __float2half(x1);
                __half l0 = __float2half(x0 - __half2float(h0));
                __half l1 = __float2half(x1 - __half2float(h1));
                __half2 hp; hp.x = h0; hp.y = h1;
                __half2 lp; lp.x = l0; lp.y = l1;
                *(__half2*)(Chi + o) = hp;
                *(__half2*)(Clo + o) = lp;
            }
        }
}

// ================= GEMM2 (NN fp16, 3 products): S = pW @ qT + softmax partials =================
static constexpr int STAGE2 = 4 * MATB;    // pWh, pWl, qTh, qTl = 64KB
static constexpr int SMEM2  = 3 * STAGE2;  // 192KB

__global__ void __launch_bounds__(512, 1)
gemm2(const __half* __restrict__ Ahi, const __half* __restrict__ Alo,
      const __half* __restrict__ Bhi, const __half* __restrict__ Blo,
      float* __restrict__ Cf, float2* __restrict__ gPart)
{
    extern __shared__ char smem[];
    const uint32_t sbase = smem_u32(smem);
    const int tid = threadIdx.x, lane = tid & 31, wid = tid >> 5;
    const int wm = wid >> 2, wn = wid & 3;
    const int b = blockIdx.z, m0 = blockIdx.y * 128, n0 = blockIdx.x * 128;

    const char* gA[2] = { (const char*)(Ahi + (size_t)b * TT + (size_t)m0 * 1024),
                          (const char*)(Alo + (size_t)b * TT + (size_t)m0 * 1024) };
    const char* gB[2] = { (const char*)(Bhi + (size_t)b * TT) + (size_t)n0 * 2,
                          (const char*)(Blo + (size_t)b * TT) + (size_t)n0 * 2 };

    const int crow[2] = { tid >> 3, (tid + 512) >> 3 };
    const int ccol = tid & 7;
    const int brow[2] = { tid >> 4, (tid + 512) >> 4 };
    const int bcol = tid & 15;

    auto issue_stage = [&](int buf, int kt) {
        const uint32_t sb = sbase + buf * STAGE2;
        const size_t kb = (size_t)kt * 128;
        #pragma unroll
        for (int m = 0; m < 2; m++) {
            const uint32_t mb = sb + m * MATB;
            #pragma unroll
            for (int t = 0; t < 2; t++) {
                const int r = crow[t];
                cp16(mb + r * 128 + ((ccol ^ (r & 7)) * 16),
                     gA[m] + (size_t)r * 2048 + kb + ccol * 16);
            }
        }
        #pragma unroll
        for (int m = 0; m < 2; m++) {
            const uint32_t mb = sb + (2 + m) * MATB;
            #pragma unroll
            for (int t = 0; t < 2; t++) {
                const int r = brow[t];
                cp16(mb + r * 256 + ((bcol ^ (r & 7)) * 16),
                     gB[m] + (size_t)(kt * 64 + r) * 2048 + bcol * 16);
            }
        }
        cp_commit();
    };

    float acc[2][4][4];
    #pragma unroll
    for (int i = 0; i < 2; i++)
        #pragma unroll
        for (int j = 0; j < 4; j++)
            #pragma unroll
            for (int t = 0; t < 4; t++) acc[i][j][t] = 0.f;

    issue_stage(0, 0);
    issue_stage(1, 1);

    const int lrow = lane & 15, lhi = lane >> 4;
    const int swz = lrow & 7;
    uint32_t koff[4];
    #pragma unroll
    for (int ks = 0; ks < 4; ks++) koff[ks] = (uint32_t)(((ks * 2 + lhi) ^ swz) * 16);

    const uint32_t arow_off = (uint32_t)(wm * 32 + lrow) * 128;
    uint32_t tb_base[2];
    #pragma unroll
    for (int nj = 0; nj < 2; nj++) {
        const int cn = wn * 4 + nj * 2 + lhi;
        tb_base[nj] = (uint32_t)(lrow * 256 + ((cn ^ swz) * 16));
    }

    #pragma unroll 1
    for (int i = 0; i < 16; i++) {
        if (i < 15) cp_wait<1>(); else cp_wait<0>();
        __syncthreads();
        if (i + 2 < 16) issue_stage((i + 2) % 3, i + 2);

        const uint32_t sb = sbase + (i % 3) * STAGE2;
        const uint32_t sAh = sb, sAl = sb + MATB, sBh = sb + 2 * MATB, sBl = sb + 3 * MATB;

        #pragma unroll
        for (int ks = 0; ks < 4; ks++) {
            const uint32_t kb = koff[ks];
            uint32_t ah[2][4], al[2][4];
            #pragma unroll
            for (int mi = 0; mi < 2; mi++) {
                const uint32_t ro = arow_off + (uint32_t)(mi * 16) * 128 + kb;
                ldsm4(ah[mi], sAh + ro);
                ldsm4(al[mi], sAl + ro);
            }
            uint32_t bh[4][2], bl[4][2];
            #pragma unroll
            for (int nj = 0; nj < 2; nj++) {
                const uint32_t ro = (uint32_t)(ks * 4096) + tb_base[nj];
                uint32_t r[4];
                ldsm4t(r, sBh + ro);
                bh[2*nj][0] = r[0]; bh[2*nj][1] = r[1];
                bh[2*nj+1][0] = r[2]; bh[2*nj+1][1] = r[3];
                ldsm4t(r, sBl + ro);
                bl[2*nj][0] = r[0]; bl[2*nj][1] = r[1];
                bl[2*nj+1][0] = r[2]; bl[2*nj+1][1] = r[3];
            }
            #pragma unroll
            for (int mi = 0; mi < 2; mi++)
                #pragma unroll
                for (int ni = 0; ni < 4; ni++) {
                    mma16816h(acc[mi][ni], ah[mi], bh[ni][0], bh[ni][1]);  // hh
                    mma16816h(acc[mi][ni], ah[mi], bl[ni][0], bl[ni][1]);  // hl
                    mma16816h(acc[mi][ni], al[mi], bh[ni][0], bh[ni][1]);  // lh
                }
        }
    }

    // epilogue: store S fp32
    const int er = m0 + wm * 32 + (lane >> 2);
    const int ec = n0 + wn * 32 + (lane & 3) * 2;
    #pragma unroll
    for (int mi = 0; mi < 2; mi++)
        #pragma unroll
        for (int ni = 0; ni < 4; ni++) {
            const int r0 = er + mi * 16, c = ec + ni * 8;
            const size_t o0 = (size_t)b * TT + (size_t)r0 * 1024 + c;
            *(float2*)(Cf + o0)            = make_float2(acc[mi][ni][0], acc[mi][ni][1]);
            *(float2*)(Cf + o0 + 8 * 1024) = make_float2(acc[mi][ni][2], acc[mi][ni][3]);
        }

    // per-CTA column softmax partials
    float pm[8], pz[8];
    #pragma unroll
    for (int ni = 0; ni < 4; ni++)
        #pragma unroll
        for (int pr = 0; pr < 2; pr++) {
            float v0 = acc[0][ni][pr],   v1 = acc[0][ni][pr+2];
            float v2 = acc[1][ni][pr],   v3 = acc[1][ni][pr+2];
            float m = fmaxf(fmaxf(v0, v1), fmaxf(v2, v3));
            float z = __expf(v0 - m) + __expf(v1 - m) + __expf(v2 - m) + __expf(v3 - m);
            pm[ni * 2 + pr] = m;
            pz[ni * 2 + pr] = z;
        }
    #pragma unroll
    for (int t = 0; t < 8; t++) {
        float m = pm[t], z = pz[t];
        #pragma unroll
        for (int off = 4; off < 32; off <<= 1) {
            float om = __shfl_xor_sync(0xffffffffu, m, off);
            float oz = __shfl_xor_sync(0xffffffffu, z, off);
            float nm = fmaxf(m, om);
            z = z * __expf(m - nm) + oz * __expf(om - nm);
            m = nm;
        }
        pm[t] = m; pz[t] = z;
    }
    __syncthreads();
    float2* part = (float2*)smem;
    if (lane < 4) {
        #pragma unroll
        for (int ni = 0; ni < 4; ni++)
            #pragma unroll
            for (int pr = 0; pr < 2; pr++) {
                const int ci = ni * 8 + lane * 2 + pr;
                part[(wm * 4 + wn) * 32 + ci] = make_float2(pm[ni*2+pr], pz[ni*2+pr]);
            }
    }
    __syncthreads();
    if (tid < 128) {
        const int wnn = tid >> 5, ci = tid & 31;
        float m = -1e30f, z = 0.f;
        #pragma unroll
        for (int w = 0; w < 4; w++) {
            float2 pv = part[(w * 4 + wnn) * 32 + ci];
            float nm = fmaxf(m, pv.x);
            z = z * __expf(m - nm) + pv.y * __expf(pv.x - nm);
            m = nm;
        }
        const int cg = n0 + wnn * 32 + ci;
        gPart[((size_t)b * 8 + blockIdx.y) * 1024 + cg] = make_float2(m, z);
    }
}

// ================= GEMM3 (NN fp16, single product, CTA 128x256): out = Eh @ qh =================
static constexpr int MATB3A = 128 * 128;   // 16KB A tile
static constexpr int MATB3B = 64 * 512;    // 32KB B tile (64 k-rows x 512B)
static constexpr int STAGE3 = MATB3A + MATB3B;  // 48KB
static constexpr int SMEM3  = 3 * STAGE3;       // 144KB

__global__ void __launch_bounds__(512, 1)
gemm_f16(const __half* __restrict__ Ahi, const __half* __restrict__ Bq,
         float* __restrict__ Cf)
{
    extern __shared__ char smem[];
    const uint32_t sbase = smem_u32(smem);
    const int tid = threadIdx.x, lane = tid & 31, wid = tid >> 5;
    const int wm = wid >> 2, wn = wid & 3;       // 4m x 4n, warp tile 32x64
    const int b = blockIdx.z, m0 = blockIdx.y * 128, n0 = blockIdx.x * 256;

    const char* gA = (const char*)(Ahi + (size_t)b * TT + (size_t)m0 * 1024);
    const char* gB = (const char*)(Bq + (size_t)b * TT) + (size_t)n0 * 2;

    // A loader: 128 rows x 8 chunks, 2 per thread
    const int crow[2] = { tid >> 3, (tid + 512) >> 3 };
    const int ccol = tid & 7;
    // B loader: 64 k-rows x 32 chunks (512B rows) = 2048 chunks, 4 per thread
    const int brow4[4] = { tid >> 5, (tid + 512) >> 5, (tid + 1024) >> 5, (tid + 1536) >> 5 };
    const int bcol = tid & 31;

    auto issue_stage = [&](int buf, int kt) {
        const uint32_t sb = sbase + buf * STAGE3;
        const size_t kb = (size_t)kt * 128;
        #pragma unroll
        for (int t = 0; t < 2; t++) {
            const int r = crow[t];
            cp16(sb + r * 128 + ((ccol ^ (r & 7)) * 16),
                 gA + (size_t)r * 2048 + kb + ccol * 16);
        }
        const uint32_t mb = sb + MATB3A;
        #pragma unroll
        for (int t = 0; t < 4; t++) {
            const int r = brow4[t];
            cp16(mb + r * 512 + ((bcol ^ (r & 7)) * 16),
                 gB + (size_t)(kt * 64 + r) * 2048 + bcol * 16);
        }
        cp_commit();
    };

    float acc[2][8][4];
    #pragma unroll
    for (int i = 0; i < 2; i++)
        #pragma unroll
        for (int j = 0; j < 8; j++)
            #pragma unroll
            for (int t = 0; t < 4; t++) acc[i][j][t] = 0.f;

    issue_stage(0, 0);
    issue_stage(1, 1);

    const int lrow = lane & 15, lhi = lane >> 4;
    const int swz = lrow & 7;
    uint32_t koff[4];
    #pragma unroll
    for (int ks = 0; ks < 4; ks++) koff[ks] = (uint32_t)(((ks * 2 + lhi) ^ swz) * 16);

    const uint32_t arow_off = (uint32_t)(wm * 32 + lrow) * 128;
    // B trans addressing: 512B rows, chunk cn = wn*8 + nj*2 + lhi, nj=0..3
    uint32_t tb_base[4];
    #pragma unroll
    for (int nj = 0; nj < 4; nj++) {
        const int cn = wn * 8 + nj * 2 + lhi;
        tb_base[nj] = (uint32_t)(lrow * 512 + ((cn ^ swz) * 16));
    }

    #pragma unroll 1
    for (int i = 0; i < 16; i++) {
        if (i < 15) cp_wait<1>(); else cp_wait<0>();
        __syncthreads();
        if (i + 2 < 16) issue_stage((i + 2) % 3, i + 2);

        const uint32_t sb = sbase + (i % 3) * STAGE3;
        const uint32_t sA_ = sb, sB_ = sb + MATB3A;

        #pragma unroll
        for (int ks = 0; ks < 4; ks++) {
            const uint32_t kb = koff[ks];
            uint32_t ah[2][4];
            #pragma unroll
            for (int mi = 0; mi < 2; mi++)
                ldsm4(ah[mi], sA_ + arow_off + (uint32_t)(mi * 16) * 128 + kb);
            uint32_t bq[8][2];
            #pragma unroll
            for (int nj = 0; nj < 4; nj++) {
                const uint32_t ro = (uint32_t)(ks * 8192) + tb_base[nj];
                uint32_t r[4];
                ldsm4t(r, sB_ + ro);
                bq[2*nj][0] = r[0]; bq[2*nj][1] = r[1];
                bq[2*nj+1][0] = r[2]; bq[2*nj+1][1] = r[3];
            }
            #pragma unroll
            for (int mi = 0; mi < 2; mi++)
                #pragma unroll
                for (int ni = 0; ni < 8; ni++)
                    mma16816h(acc[mi][ni], ah[mi], bq[ni][0], bq[ni][1]);
        }
    }

    const int er = m0 + wm * 32 + (lane >> 2);
    const int ec = n0 + wn * 64 + (lane & 3) * 2;
    #pragma unroll
    for (int mi = 0; mi < 2; mi++)
        #pragma unroll
        for (int ni = 0; ni < 8; ni++) {
            const int r0 = er + mi * 16, c = ec + ni * 8;
            const size_t o0 = (size_t)b * TT + (size_t)r0 * 1024 + c;
            *(float2*)(Cf + o0)            = make_float2(acc[mi][ni][0], acc[mi][ni][1]);
            *(float2*)(Cf + o0 + 8 * 1024) = make_float2(acc[mi][ni][2], acc[mi][ni][3]);
        }
}

// ---------------- elementwise / transpose / softmax ----------------
struct alignas(8) bh4 { __nv_bfloat16 a, b, c, d; };

__device__ __forceinline__ void split1(float x, __nv_bfloat16& h, __nv_bfloat16& l) {
    h = __float2bfloat16(x);
    l = __float2bfloat16(x - __bfloat162float(h));
}

__global__ void __launch_bounds__(256)
split2_kernel(const float* __restrict__ X, __nv_bfloat16* __restrict__ hi,
              __nv_bfloat16* __restrict__ lo)
{
    size_t i = (size_t)blockIdx.x * 256 + threadIdx.x;
    float4 v = ((const float4*)X)[i];
    bh4 h, l;
    split1(v.x, h.a, l.a); split1(v.y, h.b, l.b);
    split1(v.z, h.c, l.c); split1(v.w, h.d, l.d);
    ((bh4*)hi)[i] = h;
    ((bh4*)lo)[i] = l;
}

// q prep: straight fp16 plane (GEMM3 B) + transposed fp16 hi/lo planes (GEMM2 B)
__global__ void __launch_bounds__(256)
splitT_kernel(const float* __restrict__ in, __half* __restrict__ oh16,
              __half* __restrict__ thi, __half* __restrict__ tlo)
{
    __shared__ float t[32][33];
    const int b = blockIdx.z;
    const float* I = in + (size_t)b * TT;
    const int x = blockIdx.x * 32 + threadIdx.x;
    const int y = blockIdx.y * 32 + threadIdx.y;
    const size_t ob = (size_t)b * TT;
    #pragma unroll
    for (int j = 0; j < 32; j += 8) {
        float v = I[(size_t)(y + j) * 1024 + x];
        t[threadIdx.y + j][threadIdx.x] = v;
        oh16[ob + (size_t)(y + j) * 1024 + x] = __float2half(v);
    }
    __syncthreads();
    const int ox = blockIdx.y * 32 + threadIdx.x;
    const int oy = blockIdx.x * 32 + threadIdx.y;
    #pragma unroll
    for (int j = 0; j < 32; j += 8) {
        float v = t[threadIdx.x][threadIdx.y + j];
        __half h = __float2half(v);
        __half l = __float2half(v - __half2float(h));
        const size_t o = ob + (size_t)(oy + j) * 1024 + ox;
        thi[o] = h;
        tlo[o] = l;
    }
}

// combine per-mtile partials -> final (M, 1/Z) per column
__global__ void __launch_bounds__(256)
combine_stats(const float2* __restrict__ gPart,
              float* __restrict__ gM, float* __restrict__ gR)
{
    const int idx = blockIdx.x * 256 + threadIdx.x;
    const int b = idx >> 10, col = idx & 1023;
    float m = -1e30f, z = 0.f;
    #pragma unroll
    for (int t = 0; t < 8; t++) {
        float2 pv = gPart[((size_t)b * 8 + t) * 1024 + col];
        float nm = fmaxf(m, pv.x);
        z = z * __expf(m - nm) + pv.y * __expf(pv.x - nm);
        m = nm;
    }
    gM[idx] = m;
    gR[idx] = 1.0f / z;
}

// exp pass: single read of S -> fp16 E plane
__global__ void __launch_bounds__(256)
exp_f16(const float* __restrict__ S, const float* __restrict__ gM,
        const float* __restrict__ gR, __half* __restrict__ Eh)
{
    const int b = blockIdx.y;
    const int c = (threadIdx.x & 31);
    const int g = threadIdx.x >> 5;
    const int col = blockIdx.x * 32 + c;
    const float Mf = gM[b * 1024 + col];
    const float Rf = gR[b * 1024 + col];
    const float* Sb = S + (size_t)b * TT + col;
    __half* eh = Eh + (size_t)b * TT + col;
    #pragma unroll 4
    for (int r = g; r < 1024; r += 8) {
        float x = Sb[(size_t)r << 10];
        eh[(size_t)r << 10] = __float2half(__expf(x - Mf) * Rf);
    }
}

// ---------------- launcher ----------------
extern "C" void kernel_launch(void* const* d_in, const int* in_sizes, int n_in,
                              void* d_out, int out_size)
{
    const float* q = (const float*)d_in[0];
    const float* p = (const float*)d_in[1];
    const float* W = (const float*)d_in[2];
    float* out = (float*)d_out;

    __nv_bfloat16 *phi, *plo, *Whi, *Wlo;
    __half *qThi, *qTlo, *qh16, *pWhi, *pWlo, *Eh;
    float *S, *gM, *gR;
    float2 *gPart;
    cudaGetSymbolAddress((void**)&qThi, g_qThi); cudaGetSymbolAddress((void**)&qTlo, g_qTlo);
    cudaGetSymbolAddress((void**)&qh16, g_qh16);
    cudaGetSymbolAddress((void**)&phi, g_phi);   cudaGetSymbolAddress((void**)&plo, g_plo);
    cudaGetSymbolAddress((void**)&Whi, g_Whi);   cudaGetSymbolAddress((void**)&Wlo, g_Wlo);
    cudaGetSymbolAddress((void**)&pWhi, g_pWhi); cudaGetSymbolAddress((void**)&pWlo, g_pWlo);
    cudaGetSymbolAddress((void**)&Eh, g_Eh);
    cudaGetSymbolAddress((void**)&S, g_S);
    cudaGetSymbolAddress((void**)&gPart, g_part);
    cudaGetSymbolAddress((void**)&gM, g_M);      cudaGetSymbolAddress((void**)&gR, g_R);

    cudaFuncSetAttribute(gemm1,    cudaFuncAttributeMaxDynamicSharedMemorySize, SMEM1);
    cudaFuncSetAttribute(gemm2,    cudaFuncAttributeMaxDynamicSharedMemorySize, SMEM2);
    cudaFuncSetAttribute(gemm_f16, cudaFuncAttributeMaxDynamicSharedMemorySize, SMEM3);

    const dim3 ggrid(8, 8, 16);

    split2_kernel<<<16384, 256>>>(p, phi, plo);
    splitT_kernel<<<dim3(32, 32, 16), dim3(32, 8)>>>(q, qh16, qThi, qTlo);
    split2_kernel<<<1024,  256>>>(W, Whi, Wlo);

    // GEMM1 (NN bf16 3-prod): pW = p @ W, split-store fp16
    gemm1<<<ggrid, 512, SMEM1>>>(phi, plo, Whi, Wlo, pWhi, pWlo);
    // GEMM2 (NN fp16 3-prod): S = pW @ qT + softmax partials
    gemm2<<<ggrid, 512, SMEM2>>>(pWhi, pWlo, qThi, qTlo, S, gPart);
    // combine partials -> final column stats
    combine_stats<<<64, 256>>>(gPart, gM, gR);
    // exp: single read of S -> fp16 E
    exp_f16<<<dim3(32, 16), 256>>>(S, gM, gR, Eh);
    // GEMM3 (NN fp16 1-prod, CTA 128x256): out = Eh @ qh
    gemm_f16<<<dim3(4, 8, 16), 512, SMEM3>>>(Eh, qh16, out);
}